// round 2
// baseline (speedup 1.0000x reference)
#include <cuda_runtime.h>
#include <math.h>

#define Bn 4
#define Sn 2048
#define Dn 1024
#define Hn 16
#define DKn 64

// Scratch (alloc-free rule: __device__ globals)
__device__ float g_qkv[(size_t)3 * Bn * Hn * Sn * DKn];   // [q][b][h][s][k]  ~100MB
__device__ float g_attn[(size_t)Bn * Sn * Dn];            // [b][s][h*64+k]   ~33MB

// ---------------------------------------------------------------------------
// SGEMM: C[M,N] = A[M,K] * B[N,K]^T   (both operands K-major row-major)
// 128x128 block tile, BK=8, 8x8 per thread (split 4+4 to avoid bank conflicts)
// REMAP==0: A = x, output scattered into g_qkv ([q][b][h][s][k])
// REMAP==1: A = g_attn, output written densely to C
// ---------------------------------------------------------------------------
template <int REMAP>
__global__ void __launch_bounds__(256) sgemm_nt_kernel(
    const float* __restrict__ A, const float* __restrict__ Bm,
    float* __restrict__ C, int M, int N, int K)
{
    __shared__ float As[8][128];
    __shared__ float Bs[8][128];
    const int tid = threadIdx.x;
    const int bm = blockIdx.y * 128;
    const int bn = blockIdx.x * 128;
    const float* Ap = (REMAP == 0) ? A : (const float*)g_attn;

    const int lr = tid >> 1;          // 0..127
    const int lc = (tid & 1) << 2;    // 0 or 4
    const float* Aload = Ap + (size_t)(bm + lr) * K + lc;
    const float* Bload = Bm + (size_t)(bn + lr) * K + lc;

    const int rowb = (tid >> 4) << 2; // 0..60
    const int colb = (tid & 15) << 2; // 0..60

    float acc[8][8];
#pragma unroll
    for (int i = 0; i < 8; i++)
#pragma unroll
        for (int j = 0; j < 8; j++) acc[i][j] = 0.f;

    float4 a4 = *(const float4*)(Aload);
    float4 b4 = *(const float4*)(Bload);

    for (int k0 = 0; k0 < K; k0 += 8) {
        As[lc + 0][lr] = a4.x; As[lc + 1][lr] = a4.y;
        As[lc + 2][lr] = a4.z; As[lc + 3][lr] = a4.w;
        Bs[lc + 0][lr] = b4.x; Bs[lc + 1][lr] = b4.y;
        Bs[lc + 2][lr] = b4.z; Bs[lc + 3][lr] = b4.w;
        __syncthreads();
        if (k0 + 8 < K) {   // register prefetch of next tile
            a4 = *(const float4*)(Aload + k0 + 8);
            b4 = *(const float4*)(Bload + k0 + 8);
        }
#pragma unroll
        for (int kk = 0; kk < 8; kk++) {
            float ra[8], rb[8];
            *(float4*)&ra[0] = *(const float4*)&As[kk][rowb];
            *(float4*)&ra[4] = *(const float4*)&As[kk][64 + rowb];
            *(float4*)&rb[0] = *(const float4*)&Bs[kk][colb];
            *(float4*)&rb[4] = *(const float4*)&Bs[kk][64 + colb];
#pragma unroll
            for (int i = 0; i < 8; i++)
#pragma unroll
                for (int j = 0; j < 8; j++) acc[i][j] += ra[i] * rb[j];
        }
        __syncthreads();
    }

#pragma unroll
    for (int i = 0; i < 8; i++) {
        const int m = bm + rowb + (i & 3) + ((i >> 2) << 6);
#pragma unroll
        for (int j = 0; j < 8; j++) {
            const int n = bn + colb + (j & 3) + ((j >> 2) << 6);
            const float v = acc[i][j];
            if (REMAP == 0) {
                const int q = n >> 10;            // H*DK = 1024
                const int h = (n >> 6) & 15;
                const int kd = n & 63;
                const int b = m >> 11;            // S = 2048
                const int s = m & 2047;
                g_qkv[((((size_t)q * Bn + b) * Hn + h) * Sn + s) * DKn + kd] = v;
            } else {
                C[(size_t)m * N + n] = v;
            }
        }
    }
}

// ---------------------------------------------------------------------------
// Causal flash attention, fp32.
// Block = (b, h, 64-row q tile). 256 threads as 16x16; each thread owns a
// 4x4 micro-tile of the 64x64 score block and a 4x4 micro-tile of O.
// Smem: Qs[64][68] row-major, KPs = K^T tile [kk][s] (reused as P[r][c]),
// Vs[64][68] row-major. Pad 68 keeps float4 alignment + bank spread.
// ---------------------------------------------------------------------------
#define LDP 68
#define SMEM_FLASH (3 * 64 * LDP * 4)

__global__ void __launch_bounds__(256) flash_kernel()
{
    extern __shared__ float sm[];
    float* Qs  = sm;                 // [64][LDP]
    float* KPs = sm + 64 * LDP;      // K^T [kk][s] -> later P [r][c]
    float* Vs  = sm + 2 * 64 * LDP;  // [s][k]

    const int qt = 31 - blockIdx.x;  // largest workload first
    const int h = blockIdx.y, b = blockIdx.z;
    const int tid = threadIdx.x;
    const int tx = tid & 15, ty = tid >> 4;

    const size_t headoff = (((size_t)b * Hn + h) * Sn) * DKn;
    const size_t planesz = (size_t)Bn * Hn * Sn * DKn;
    const float* Qg = g_qkv + headoff;
    const float* Kg = g_qkv + planesz + headoff;
    const float* Vg = g_qkv + 2 * planesz + headoff;

    // Load Q tile (64x64 floats = 1024 float4, 4 per thread)
#pragma unroll
    for (int u = 0; u < 4; u++) {
        const int idx = tid + u * 256;
        const int r = idx >> 4, c = (idx & 15) << 2;
        *(float4*)(Qs + r * LDP + c) =
            *(const float4*)(Qg + (size_t)(qt * 64 + r) * DKn + c);
    }

    float m_i[4], l_i[4], o[4][4];
#pragma unroll
    for (int i = 0; i < 4; i++) {
        m_i[i] = -3.0e38f; l_i[i] = 0.f;
#pragma unroll
        for (int j = 0; j < 4; j++) o[i][j] = 0.f;
    }

    for (int kt = 0; kt <= qt; kt++) {
        __syncthreads();   // prev PV reads done / Q visible on first iter
        // K tile -> KPs transposed [kk][s]; V tile -> Vs [s][k]
#pragma unroll
        for (int u = 0; u < 4; u++) {
            const int idx = tid + u * 256;
            const int r = idx >> 4, c = (idx & 15) << 2;
            const float4 kv = *(const float4*)(Kg + (size_t)(kt * 64 + r) * DKn + c);
            KPs[(c + 0) * LDP + r] = kv.x;
            KPs[(c + 1) * LDP + r] = kv.y;
            KPs[(c + 2) * LDP + r] = kv.z;
            KPs[(c + 3) * LDP + r] = kv.w;
            *(float4*)(Vs + r * LDP + c) =
                *(const float4*)(Vg + (size_t)(kt * 64 + r) * DKn + c);
        }
        __syncthreads();

        // S = Q K^T
        float s[4][4];
#pragma unroll
        for (int i = 0; i < 4; i++)
#pragma unroll
            for (int j = 0; j < 4; j++) s[i][j] = 0.f;

#pragma unroll
        for (int kk = 0; kk < 64; kk += 4) {
            float4 q4[4], kv[4];
#pragma unroll
            for (int i = 0; i < 4; i++)
                q4[i] = *(const float4*)(Qs + (ty * 4 + i) * LDP + kk);
#pragma unroll
            for (int t = 0; t < 4; t++)
                kv[t] = *(const float4*)(KPs + (kk + t) * LDP + tx * 4);
#pragma unroll
            for (int i = 0; i < 4; i++) {
                s[i][0] += q4[i].x * kv[0].x + q4[i].y * kv[1].x + q4[i].z * kv[2].x + q4[i].w * kv[3].x;
                s[i][1] += q4[i].x * kv[0].y + q4[i].y * kv[1].y + q4[i].z * kv[2].y + q4[i].w * kv[3].y;
                s[i][2] += q4[i].x * kv[0].z + q4[i].y * kv[1].z + q4[i].z * kv[2].z + q4[i].w * kv[3].z;
                s[i][3] += q4[i].x * kv[0].w + q4[i].y * kv[1].w + q4[i].z * kv[2].w + q4[i].w * kv[3].w;
            }
        }

        const float scale = 0.125f;  // 1/sqrt(64)
        if (kt == qt) {
#pragma unroll
            for (int i = 0; i < 4; i++)
#pragma unroll
                for (int j = 0; j < 4; j++)
                    s[i][j] = (tx * 4 + j > ty * 4 + i) ? -3.0e38f : s[i][j] * scale;
        } else {
#pragma unroll
            for (int i = 0; i < 4; i++)
#pragma unroll
                for (int j = 0; j < 4; j++) s[i][j] *= scale;
        }

        // Online softmax (row groups = 16 lanes sharing ty)
        float alpha[4];
#pragma unroll
        for (int i = 0; i < 4; i++) {
            float rmax = fmaxf(fmaxf(s[i][0], s[i][1]), fmaxf(s[i][2], s[i][3]));
#pragma unroll
            for (int off = 8; off; off >>= 1)
                rmax = fmaxf(rmax, __shfl_xor_sync(0xffffffffu, rmax, off, 16));
            const float mn = fmaxf(m_i[i], rmax);
            float rsum = 0.f;
#pragma unroll
            for (int j = 0; j < 4; j++) {
                s[i][j] = __expf(s[i][j] - mn);
                rsum += s[i][j];
            }
#pragma unroll
            for (int off = 8; off; off >>= 1)
                rsum += __shfl_xor_sync(0xffffffffu, rsum, off, 16);
            alpha[i] = __expf(m_i[i] - mn);
            l_i[i] = l_i[i] * alpha[i] + rsum;
            m_i[i] = mn;
        }

        __syncthreads();   // all score-GEMM reads of KPs done before P overwrite
#pragma unroll
        for (int i = 0; i < 4; i++)
            *(float4*)(KPs + (ty * 4 + i) * LDP + tx * 4) =
                make_float4(s[i][0], s[i][1], s[i][2], s[i][3]);
        __syncthreads();

        // O = O*alpha + P V
#pragma unroll
        for (int i = 0; i < 4; i++)
#pragma unroll
            for (int j = 0; j < 4; j++) o[i][j] *= alpha[i];

#pragma unroll
        for (int c = 0; c < 64; c += 4) {
            float4 p4[4], vv[4];
#pragma unroll
            for (int i = 0; i < 4; i++)
                p4[i] = *(const float4*)(KPs + (ty * 4 + i) * LDP + c);
#pragma unroll
            for (int t = 0; t < 4; t++)
                vv[t] = *(const float4*)(Vs + (c + t) * LDP + tx * 4);
#pragma unroll
            for (int i = 0; i < 4; i++) {
                o[i][0] += p4[i].x * vv[0].x + p4[i].y * vv[1].x + p4[i].z * vv[2].x + p4[i].w * vv[3].x;
                o[i][1] += p4[i].x * vv[0].y + p4[i].y * vv[1].y + p4[i].z * vv[2].y + p4[i].w * vv[3].y;
                o[i][2] += p4[i].x * vv[0].z + p4[i].y * vv[1].z + p4[i].z * vv[2].z + p4[i].w * vv[3].z;
                o[i][3] += p4[i].x * vv[0].w + p4[i].y * vv[1].w + p4[i].z * vv[2].w + p4[i].w * vv[3].w;
            }
        }
    }

    // Epilogue: normalize, write [b][s][h*64+k]
#pragma unroll
    for (int i = 0; i < 4; i++) {
        const float inv = 1.0f / l_i[i];
        const int srow = qt * 64 + ty * 4 + i;
        *(float4*)(g_attn + ((size_t)b * Sn + srow) * Dn + h * 64 + tx * 4) =
            make_float4(o[i][0] * inv, o[i][1] * inv, o[i][2] * inv, o[i][3] * inv);
    }
}

// ---------------------------------------------------------------------------

extern "C" void kernel_launch(void* const* d_in, const int* in_sizes, int n_in,
                              void* d_out, int out_size)
{
    const float* x     = (const float*)d_in[0];  // [B,S,D]
    const float* w_qkv = (const float*)d_in[1];  // [3,H,DK,D]
    const float* w_o   = (const float*)d_in[2];  // [D,D]
    float* out = (float*)d_out;                  // [B,S,D]

    const int M = Bn * Sn;   // 8192

    // One-time, idempotent, non-stream attribute set (legal under graph capture)
    (void)cudaFuncSetAttribute(flash_kernel,
                               cudaFuncAttributeMaxDynamicSharedMemorySize, SMEM_FLASH);

    // 1) QKV projection -> g_qkv
    {
        dim3 grid(3 * Hn * DKn / 128, M / 128);  // (24, 64)
        sgemm_nt_kernel<0><<<grid, 256>>>(x, w_qkv, nullptr, M, 3 * Hn * DKn, Dn);
    }

    // 2) Causal flash attention -> g_attn
    {
        dim3 grid(Sn / 64, Hn, Bn);  // (32, 16, 4)
        flash_kernel<<<grid, 256, SMEM_FLASH>>>();
    }

    // 3) Output projection -> out
    {
        dim3 grid(Dn / 128, M / 128);  // (8, 64)
        sgemm_nt_kernel<1><<<grid, 256>>>(nullptr, w_o, out, M, Dn, Dn);
    }
}

// round 5
// speedup vs baseline: 1.3339x; 1.3339x over previous
#include <cuda_runtime.h>
#include <cuda_bf16.h>
#include <cstdint>
#include <cstddef>
#include <math.h>

#define Bn 4
#define Sn 2048
#define Dn 1024
#define Hn 16
#define DKn 64

// ---------------------------------------------------------------------------
// Scratch (alloc-free rule: __device__ globals)
// ---------------------------------------------------------------------------
__device__ float g_qkv[(size_t)3 * Bn * Hn * Sn * DKn];          // [q][b][h][s][k] fp32
__device__ __nv_bfloat16 g_xhi[(size_t)Bn * Sn * Dn];            // x split
__device__ __nv_bfloat16 g_xlo[(size_t)Bn * Sn * Dn];
__device__ __nv_bfloat16 g_whi[(size_t)3 * Hn * DKn * Dn];       // w_qkv split
__device__ __nv_bfloat16 g_wlo[(size_t)3 * Hn * DKn * Dn];
__device__ __nv_bfloat16 g_ahi[(size_t)Bn * Sn * Dn];            // attn out split
__device__ __nv_bfloat16 g_alo[(size_t)Bn * Sn * Dn];
__device__ __nv_bfloat16 g_wohi[(size_t)Dn * Dn];                // w_o split
__device__ __nv_bfloat16 g_wolo[(size_t)Dn * Dn];

// ---------------------------------------------------------------------------
// PTX helpers (sm_100 baseline: cp.async + ldmatrix + mma.sync only)
// ---------------------------------------------------------------------------
__device__ __forceinline__ uint32_t smem_u32(const void* p) {
    uint32_t a;
    asm("{ .reg .u64 t; cvta.to.shared.u64 t, %1; cvt.u32.u64 %0, t; }"
        : "=r"(a) : "l"(p));
    return a;
}

__device__ __forceinline__ void cp16(uint32_t dst, const void* src) {
    asm volatile("cp.async.cg.shared.global [%0], [%1], 16;"
                 :: "r"(dst), "l"(src));
}
#define CP_COMMIT() asm volatile("cp.async.commit_group;" ::: "memory")
#define CP_WAIT(n)  asm volatile("cp.async.wait_group %0;" :: "n"(n) : "memory")

__device__ __forceinline__ void ldsm4(uint32_t* r, uint32_t addr) {
    asm volatile("ldmatrix.sync.aligned.m8n8.x4.shared.b16 {%0,%1,%2,%3}, [%4];"
                 : "=r"(r[0]), "=r"(r[1]), "=r"(r[2]), "=r"(r[3]) : "r"(addr));
}
__device__ __forceinline__ void ldsm2(uint32_t* r, uint32_t addr) {
    asm volatile("ldmatrix.sync.aligned.m8n8.x2.shared.b16 {%0,%1}, [%2];"
                 : "=r"(r[0]), "=r"(r[1]) : "r"(addr));
}

__device__ __forceinline__ void mma16816(float* d, const uint32_t* a, const uint32_t* b) {
    asm volatile("mma.sync.aligned.m16n8k16.row.col.f32.bf16.bf16.f32 "
                 "{%0,%1,%2,%3}, {%4,%5,%6,%7}, {%8,%9}, {%0,%1,%2,%3};"
                 : "+f"(d[0]), "+f"(d[1]), "+f"(d[2]), "+f"(d[3])
                 : "r"(a[0]), "r"(a[1]), "r"(a[2]), "r"(a[3]), "r"(b[0]), "r"(b[1]));
}

union B4 { __nv_bfloat16 b[4]; uint2 u; };

// ---------------------------------------------------------------------------
// fp32 -> (hi, lo) bf16 split
// ---------------------------------------------------------------------------
__global__ void __launch_bounds__(256) split_kernel(
    const float4* __restrict__ in, uint2* __restrict__ hi, uint2* __restrict__ lo, int n4)
{
    int i = blockIdx.x * 256 + threadIdx.x;
    if (i >= n4) return;
    float4 v = in[i];
    B4 H, L;
    H.b[0] = __float2bfloat16(v.x); L.b[0] = __float2bfloat16(v.x - __bfloat162float(H.b[0]));
    H.b[1] = __float2bfloat16(v.y); L.b[1] = __float2bfloat16(v.y - __bfloat162float(H.b[1]));
    H.b[2] = __float2bfloat16(v.z); L.b[2] = __float2bfloat16(v.z - __bfloat162float(H.b[2]));
    H.b[3] = __float2bfloat16(v.w); L.b[3] = __float2bfloat16(v.w - __bfloat162float(H.b[3]));
    hi[i] = H.u;
    lo[i] = L.u;
}

// ---------------------------------------------------------------------------
// mma.sync bf16x3 GEMM:  C[M,N] = A[M,K] * B[N,K]^T, fp32 accumulate.
// 128x128 CTA tile, BK=32, 8 warps (2x4), warp tile 64x32 (4x4 mma tiles).
// 3-stage cp.async pipeline. Smem pad: row stride 40 bf16 (80B).
// REMAP==0: scatter into g_qkv ([q][b][h][s][k]); REMAP==1: dense C row-major.
// ---------------------------------------------------------------------------
#define LDS2      40                      // bf16 elems per smem row (32 + 8 pad)
#define MAT_ELEMS (128 * LDS2)            // 5120 bf16 = 10240 B
#define STG_ELEMS (4 * MAT_ELEMS)         // Ahi,Alo,Bhi,Blo
#define STG_BYTES (STG_ELEMS * 2)         // 40960
#define G_SMEM    (3 * STG_BYTES)         // 122880

template <int REMAP>
__global__ void __launch_bounds__(256) gemm_bf16x3(
    const __nv_bfloat16* __restrict__ Ahi, const __nv_bfloat16* __restrict__ Alo,
    const __nv_bfloat16* __restrict__ Bhi, const __nv_bfloat16* __restrict__ Blo,
    float* __restrict__ C, int M, int N, int K)
{
    extern __shared__ __nv_bfloat16 sm[];
    const uint32_t sb = smem_u32(sm);
    const int tid = threadIdx.x;
    const int wid = tid >> 5, lane = tid & 31;
    const int wm = wid >> 2, wn = wid & 3;          // 2 x 4 warp grid
    const int bm = blockIdx.y * 128, bn = blockIdx.x * 128;
    const int NC = K >> 5;                          // BK = 32
    const size_t ldb = (size_t)K * 2;               // row stride bytes

    const char* gA[2] = { (const char*)Ahi + (size_t)bm * ldb,
                          (const char*)Alo + (size_t)bm * ldb };
    const char* gB[2] = { (const char*)Bhi + (size_t)bn * ldb,
                          (const char*)Blo + (size_t)bn * ldb };

    // Fill stage s with K-chunk c. 4 matrices x 512 x 16B chunks; 8 per thread.
    auto fill = [&](int s, int c) {
        const size_t kb = (size_t)c << 6;           // c*32 elems *2B
        const uint32_t base = sb + s * STG_BYTES;
#pragma unroll
        for (int mat = 0; mat < 4; mat++) {
            const char* g = (mat < 2) ? gA[mat] : gB[mat - 2];
#pragma unroll
            for (int u = 0; u < 2; u++) {
                const int ch = (tid << 1) | u;      // 0..511
                const int row = ch >> 2, col = ch & 3;
                cp16(base + mat * (MAT_ELEMS * 2) + row * (LDS2 * 2) + col * 16,
                     g + (size_t)row * ldb + kb + col * 16);
            }
        }
        CP_COMMIT();
    };

    fill(0, 0);
    if (NC > 1) fill(1, 1);
    if (NC > 2) fill(2, 2);

    float acc[4][4][4];
#pragma unroll
    for (int i = 0; i < 4; i++)
#pragma unroll
        for (int j = 0; j < 4; j++)
#pragma unroll
            for (int e = 0; e < 4; e++) acc[i][j][e] = 0.f;

    // ldmatrix lane addressing (bf16-elem offsets within a tile)
    const int aRow = (lane & 15);                   // + tile base row
    const int aColHalf = (lane >> 4) << 3;          // 0 or 8
    const int bRow = (lane & 7);
    const int bColHalf = ((lane >> 3) & 1) << 3;    // 0 or 8 (only lanes 0-15 used)

    for (int c = 0; c < NC; c++) {
        const int s = c % 3;
        const int rem = NC - 1 - c;
        if (rem >= 2) { CP_WAIT(2); } else if (rem == 1) { CP_WAIT(1); } else { CP_WAIT(0); }
        __syncthreads();

        const uint32_t stg = sb + s * STG_BYTES;
        const uint32_t aHiB = stg;
        const uint32_t aLoB = stg + 1 * (MAT_ELEMS * 2);
        const uint32_t bHiB = stg + 2 * (MAT_ELEMS * 2);
        const uint32_t bLoB = stg + 3 * (MAT_ELEMS * 2);

#pragma unroll
        for (int k0 = 0; k0 < 32; k0 += 16) {
            uint32_t ah[4][4], al[4][4], bh[4][2], bl[4][2];
#pragma unroll
            for (int i = 0; i < 4; i++) {
                const uint32_t off =
                    (uint32_t)((wm * 64 + i * 16 + aRow) * LDS2 + k0 + aColHalf) * 2;
                ldsm4(ah[i], aHiB + off);
                ldsm4(al[i], aLoB + off);
            }
#pragma unroll
            for (int j = 0; j < 4; j++) {
                const uint32_t off =
                    (uint32_t)((wn * 32 + j * 8 + bRow) * LDS2 + k0 + bColHalf) * 2;
                ldsm2(bh[j], bHiB + off);
                ldsm2(bl[j], bLoB + off);
            }
#pragma unroll
            for (int i = 0; i < 4; i++)
#pragma unroll
                for (int j = 0; j < 4; j++) {
                    mma16816(acc[i][j], ah[i], bh[j]);   // hi*hi
                    mma16816(acc[i][j], ah[i], bl[j]);   // hi*lo
                    mma16816(acc[i][j], al[i], bh[j]);   // lo*hi
                }
        }

        __syncthreads();                  // everyone done reading stage s
        if (c + 3 < NC) fill(s, c + 3);   // refill s while c+1,c+2 compute
    }

    // Epilogue: fragment registers -> global (float2 = 8B, 4 lanes/row = 32B sector)
    const int fr = lane >> 2;             // 0..7
    const int fc = (lane & 3) << 1;       // 0,2,4,6
#pragma unroll
    for (int i = 0; i < 4; i++) {
#pragma unroll
        for (int j = 0; j < 4; j++) {
            const int n = bn + wn * 32 + j * 8 + fc;
#pragma unroll
            for (int half = 0; half < 2; half++) {
                const int m = bm + wm * 64 + i * 16 + fr + half * 8;
                const float2 v = make_float2(acc[i][j][half * 2], acc[i][j][half * 2 + 1]);
                if (REMAP == 0) {
                    const int q = n >> 10, h = (n >> 6) & 15, kd = n & 63;
                    const int b = m >> 11, s2 = m & 2047;
                    *(float2*)&g_qkv[((((size_t)q * Bn + b) * Hn + h) * Sn + s2) * DKn + kd] = v;
                } else {
                    *(float2*)&C[(size_t)m * N + n] = v;
                }
            }
        }
    }
}

// ---------------------------------------------------------------------------
// Causal flash attention, fp32; epilogue emits split bf16 (feeds GEMM2).
// ---------------------------------------------------------------------------
#define LDP 68
#define SMEM_FLASH (3 * 64 * LDP * 4)

__global__ void __launch_bounds__(256) flash_kernel()
{
    extern __shared__ float smf[];
    float* Qs  = smf;
    float* KPs = smf + 64 * LDP;
    float* Vs  = smf + 2 * 64 * LDP;

    const int qt = 31 - blockIdx.x;
    const int h = blockIdx.y, b = blockIdx.z;
    const int tid = threadIdx.x;
    const int tx = tid & 15, ty = tid >> 4;

    const size_t headoff = (((size_t)b * Hn + h) * Sn) * DKn;
    const size_t planesz = (size_t)Bn * Hn * Sn * DKn;
    const float* Qg = g_qkv + headoff;
    const float* Kg = g_qkv + planesz + headoff;
    const float* Vg = g_qkv + 2 * planesz + headoff;

#pragma unroll
    for (int u = 0; u < 4; u++) {
        const int idx = tid + u * 256;
        const int r = idx >> 4, c = (idx & 15) << 2;
        *(float4*)(Qs + r * LDP + c) =
            *(const float4*)(Qg + (size_t)(qt * 64 + r) * DKn + c);
    }

    float m_i[4], l_i[4], o[4][4];
#pragma unroll
    for (int i = 0; i < 4; i++) {
        m_i[i] = -3.0e38f; l_i[i] = 0.f;
#pragma unroll
        for (int j = 0; j < 4; j++) o[i][j] = 0.f;
    }

    for (int kt = 0; kt <= qt; kt++) {
        __syncthreads();
#pragma unroll
        for (int u = 0; u < 4; u++) {
            const int idx = tid + u * 256;
            const int r = idx >> 4, c = (idx & 15) << 2;
            const float4 kv = *(const float4*)(Kg + (size_t)(kt * 64 + r) * DKn + c);
            KPs[(c + 0) * LDP + r] = kv.x;
            KPs[(c + 1) * LDP + r] = kv.y;
            KPs[(c + 2) * LDP + r] = kv.z;
            KPs[(c + 3) * LDP + r] = kv.w;
            *(float4*)(Vs + r * LDP + c) =
                *(const float4*)(Vg + (size_t)(kt * 64 + r) * DKn + c);
        }
        __syncthreads();

        float s[4][4];
#pragma unroll
        for (int i = 0; i < 4; i++)
#pragma unroll
            for (int j = 0; j < 4; j++) s[i][j] = 0.f;

#pragma unroll
        for (int kk = 0; kk < 64; kk += 4) {
            float4 q4[4], kv[4];
#pragma unroll
            for (int i = 0; i < 4; i++)
                q4[i] = *(const float4*)(Qs + (ty * 4 + i) * LDP + kk);
#pragma unroll
            for (int t = 0; t < 4; t++)
                kv[t] = *(const float4*)(KPs + (kk + t) * LDP + tx * 4);
#pragma unroll
            for (int i = 0; i < 4; i++) {
                s[i][0] += q4[i].x * kv[0].x + q4[i].y * kv[1].x + q4[i].z * kv[2].x + q4[i].w * kv[3].x;
                s[i][1] += q4[i].x * kv[0].y + q4[i].y * kv[1].y + q4[i].z * kv[2].y + q4[i].w * kv[3].y;
                s[i][2] += q4[i].x * kv[0].z + q4[i].y * kv[1].z + q4[i].z * kv[2].z + q4[i].w * kv[3].z;
                s[i][3] += q4[i].x * kv[0].w + q4[i].y * kv[1].w + q4[i].z * kv[2].w + q4[i].w * kv[3].w;
            }
        }

        const float scale = 0.125f;
        if (kt == qt) {
#pragma unroll
            for (int i = 0; i < 4; i++)
#pragma unroll
                for (int j = 0; j < 4; j++)
                    s[i][j] = (tx * 4 + j > ty * 4 + i) ? -3.0e38f : s[i][j] * scale;
        } else {
#pragma unroll
            for (int i = 0; i < 4; i++)
#pragma unroll
                for (int j = 0; j < 4; j++) s[i][j] *= scale;
        }

        float alpha[4];
#pragma unroll
        for (int i = 0; i < 4; i++) {
            float rmax = fmaxf(fmaxf(s[i][0], s[i][1]), fmaxf(s[i][2], s[i][3]));
#pragma unroll
            for (int off = 8; off; off >>= 1)
                rmax = fmaxf(rmax, __shfl_xor_sync(0xffffffffu, rmax, off, 16));
            const float mn = fmaxf(m_i[i], rmax);
            float rsum = 0.f;
#pragma unroll
            for (int j = 0; j < 4; j++) {
                s[i][j] = __expf(s[i][j] - mn);
                rsum += s[i][j];
            }
#pragma unroll
            for (int off = 8; off; off >>= 1)
                rsum += __shfl_xor_sync(0xffffffffu, rsum, off, 16);
            alpha[i] = __expf(m_i[i] - mn);
            l_i[i] = l_i[i] * alpha[i] + rsum;
            m_i[i] = mn;
        }

        __syncthreads();
#pragma unroll
        for (int i = 0; i < 4; i++)
            *(float4*)(KPs + (ty * 4 + i) * LDP + tx * 4) =
                make_float4(s[i][0], s[i][1], s[i][2], s[i][3]);
        __syncthreads();

#pragma unroll
        for (int i = 0; i < 4; i++)
#pragma unroll
            for (int j = 0; j < 4; j++) o[i][j] *= alpha[i];

#pragma unroll
        for (int c = 0; c < 64; c += 4) {
            float4 p4[4], vv[4];
#pragma unroll
            for (int i = 0; i < 4; i++)
                p4[i] = *(const float4*)(KPs + (ty * 4 + i) * LDP + c);
#pragma unroll
            for (int t = 0; t < 4; t++)
                vv[t] = *(const float4*)(Vs + (c + t) * LDP + tx * 4);
#pragma unroll
            for (int i = 0; i < 4; i++) {
                o[i][0] += p4[i].x * vv[0].x + p4[i].y * vv[1].x + p4[i].z * vv[2].x + p4[i].w * vv[3].x;
                o[i][1] += p4[i].x * vv[0].y + p4[i].y * vv[1].y + p4[i].z * vv[2].y + p4[i].w * vv[3].y;
                o[i][2] += p4[i].x * vv[0].z + p4[i].y * vv[1].z + p4[i].z * vv[2].z + p4[i].w * vv[3].z;
                o[i][3] += p4[i].x * vv[0].w + p4[i].y * vv[1].w + p4[i].z * vv[2].w + p4[i].w * vv[3].w;
            }
        }
    }

#pragma unroll
    for (int i = 0; i < 4; i++) {
        const float inv = 1.0f / l_i[i];
        const int srow = qt * 64 + ty * 4 + i;
        const size_t di = ((size_t)b * Sn + srow) * Dn + h * 64 + tx * 4;
        float v[4] = { o[i][0] * inv, o[i][1] * inv, o[i][2] * inv, o[i][3] * inv };
        B4 H, L;
#pragma unroll
        for (int j = 0; j < 4; j++) {
            H.b[j] = __float2bfloat16(v[j]);
            L.b[j] = __float2bfloat16(v[j] - __bfloat162float(H.b[j]));
        }
        *(uint2*)(g_ahi + di) = H.u;
        *(uint2*)(g_alo + di) = L.u;
    }
}

// ---------------------------------------------------------------------------

extern "C" void kernel_launch(void* const* d_in, const int* in_sizes, int n_in,
                              void* d_out, int out_size)
{
    const float* x     = (const float*)d_in[0];  // [B,S,D]
    const float* w_qkv = (const float*)d_in[1];  // [3,H,DK,D]
    const float* w_o   = (const float*)d_in[2];  // [D,D]
    float* out = (float*)d_out;                  // [B,S,D]

    const int M = Bn * Sn;   // 8192

    (void)cudaFuncSetAttribute(flash_kernel,
                               cudaFuncAttributeMaxDynamicSharedMemorySize, SMEM_FLASH);
    (void)cudaFuncSetAttribute(gemm_bf16x3<0>,
                               cudaFuncAttributeMaxDynamicSharedMemorySize, G_SMEM);
    (void)cudaFuncSetAttribute(gemm_bf16x3<1>,
                               cudaFuncAttributeMaxDynamicSharedMemorySize, G_SMEM);

    __nv_bfloat16 *xhi, *xlo, *whi, *wlo, *ahi, *alo, *wohi, *wolo;
    (void)cudaGetSymbolAddress((void**)&xhi, g_xhi);
    (void)cudaGetSymbolAddress((void**)&xlo, g_xlo);
    (void)cudaGetSymbolAddress((void**)&whi, g_whi);
    (void)cudaGetSymbolAddress((void**)&wlo, g_wlo);
    (void)cudaGetSymbolAddress((void**)&ahi, g_ahi);
    (void)cudaGetSymbolAddress((void**)&alo, g_alo);
    (void)cudaGetSymbolAddress((void**)&wohi, g_wohi);
    (void)cudaGetSymbolAddress((void**)&wolo, g_wolo);

    // 0) fp32 -> bf16 hi/lo splits
    {
        int n4 = M * Dn / 4;
        split_kernel<<<(n4 + 255) / 256, 256>>>((const float4*)x, (uint2*)xhi, (uint2*)xlo, n4);
        n4 = 3 * Hn * DKn * Dn / 4;
        split_kernel<<<(n4 + 255) / 256, 256>>>((const float4*)w_qkv, (uint2*)whi, (uint2*)wlo, n4);
        n4 = Dn * Dn / 4;
        split_kernel<<<(n4 + 255) / 256, 256>>>((const float4*)w_o, (uint2*)wohi, (uint2*)wolo, n4);
    }

    // 1) QKV projection (mma.sync bf16x3) -> g_qkv
    {
        dim3 grid(3 * Hn * DKn / 128, M / 128);  // (24, 64)
        gemm_bf16x3<0><<<grid, 256, G_SMEM>>>(xhi, xlo, whi, wlo, nullptr, M, 3 * Hn * DKn, Dn);
    }

    // 2) Causal flash attention -> g_ahi/g_alo
    {
        dim3 grid(Sn / 64, Hn, Bn);  // (32, 16, 4)
        flash_kernel<<<grid, 256, SMEM_FLASH>>>();
    }

    // 3) Output projection (mma.sync bf16x3) -> out
    {
        dim3 grid(Dn / 128, M / 128);  // (8, 64)
        gemm_bf16x3<1><<<grid, 256, G_SMEM>>>(ahi, alo, wohi, wolo, out, M, Dn, Dn);
    }
}

// round 6
// speedup vs baseline: 3.1378x; 2.3522x over previous
#include <cuda_runtime.h>
#include <cstdint>
#include <cstddef>
#include <math.h>

#define Bn 4
#define Sn 2048
#define Dn 1024
#define Hn 16
#define DKn 64

// ---------------------------------------------------------------------------
// Scratch (alloc-free rule: __device__ globals)
// ---------------------------------------------------------------------------
__device__ float g_qkv[(size_t)3 * Bn * Hn * Sn * DKn];   // [q][b][h][s][k], tf32-valued
__device__ float g_attn[(size_t)Bn * Sn * Dn];            // [b][s][h*64+d], tf32-valued
__device__ float g_xt[(size_t)Bn * Sn * Dn];              // rna(x)
__device__ float g_wt[(size_t)3 * Hn * DKn * Dn];         // rna(w_qkv)
__device__ float g_wot[(size_t)Dn * Dn];                  // rna(w_o)

// ---------------------------------------------------------------------------
// PTX helpers (sm_100 baseline)
// ---------------------------------------------------------------------------
__device__ __forceinline__ uint32_t smem_u32(const void* p) {
    uint32_t a;
    asm("{ .reg .u64 t; cvta.to.shared.u64 t, %1; cvt.u32.u64 %0, t; }"
        : "=r"(a) : "l"(p));
    return a;
}

__device__ __forceinline__ void cp16(uint32_t dst, const void* src) {
    asm volatile("cp.async.cg.shared.global [%0], [%1], 16;"
                 :: "r"(dst), "l"(src));
}
#define CP_COMMIT() asm volatile("cp.async.commit_group;" ::: "memory")
#define CP_WAIT(n)  asm volatile("cp.async.wait_group %0;" :: "n"(n) : "memory")

__device__ __forceinline__ float tf32r(float x) {
    uint32_t u;
    asm("cvt.rna.tf32.f32 %0, %1;" : "=r"(u) : "f"(x));
    return __uint_as_float(u);
}

__device__ __forceinline__ void mma_tf32(float* d, const uint32_t* a, const uint32_t* b) {
    asm volatile("mma.sync.aligned.m16n8k8.row.col.f32.tf32.tf32.f32 "
                 "{%0,%1,%2,%3}, {%4,%5,%6,%7}, {%8,%9}, {%0,%1,%2,%3};"
                 : "+f"(d[0]), "+f"(d[1]), "+f"(d[2]), "+f"(d[3])
                 : "r"(a[0]), "r"(a[1]), "r"(a[2]), "r"(a[3]), "r"(b[0]), "r"(b[1]));
}

// ---------------------------------------------------------------------------
// Elementwise rna(tf32) pre-pass
// ---------------------------------------------------------------------------
__global__ void __launch_bounds__(256) cvt_kernel(
    const float4* __restrict__ in, float4* __restrict__ outp, int n4)
{
    int i = blockIdx.x * 256 + threadIdx.x;
    if (i >= n4) return;
    float4 v = in[i];
    v.x = tf32r(v.x); v.y = tf32r(v.y); v.z = tf32r(v.z); v.w = tf32r(v.w);
    outp[i] = v;
}

// ---------------------------------------------------------------------------
// tf32 GEMM: C[M,N] = A[M,K] * B[N,K]^T, fp32 accumulate.
// 128x128 CTA tile, BK=32, 8 warps (2x4), warp tile 64x32, 3-stage cp.async.
// Smem stride 36 floats -> fragment lds are bank-conflict-free.
// REMAP==0: cvt+scatter into g_qkv; REMAP==1: dense C row-major.
// ---------------------------------------------------------------------------
#define GLDS  36
#define GMATF (128 * GLDS)            // floats per matrix tile
#define GSTG  (2 * GMATF * 4)         // bytes per stage = 36864
#define G_SMEM (3 * GSTG)             // 110592

template <int REMAP>
__global__ void __launch_bounds__(256, 2) gemm_tf32(
    const float* __restrict__ A, const float* __restrict__ Bm,
    float* __restrict__ C, int M, int N, int K)
{
    extern __shared__ float sg[];
    const uint32_t sb = smem_u32(sg);
    const int tid = threadIdx.x, lane = tid & 31, wid = tid >> 5;
    const int wm = wid >> 2, wn = wid & 3;
    const int lr = lane >> 2, lc = lane & 3;
    const int bm = blockIdx.y * 128, bn = blockIdx.x * 128;
    const int NC = K >> 5;

    const char* gA = (const char*)(A + (size_t)bm * K);
    const char* gB = (const char*)(Bm + (size_t)bn * K);

    auto fill = [&](int s, int c) {
        const uint32_t base = sb + s * GSTG;
        const int kof = c * 32;
#pragma unroll
        for (int u = 0; u < 4; u++) {
            const int ch = tid + u * 256;              // 0..1023
            const int row = ch >> 3, col = (ch & 7) << 2;
            cp16(base + (uint32_t)(row * GLDS + col) * 4,
                 gA + ((size_t)row * K + kof + col) * 4);
            cp16(base + (uint32_t)GMATF * 4 + (uint32_t)(row * GLDS + col) * 4,
                 gB + ((size_t)row * K + kof + col) * 4);
        }
        CP_COMMIT();
    };

    fill(0, 0);
    if (NC > 1) fill(1, 1);
    if (NC > 2) fill(2, 2);

    float acc[4][4][4];
#pragma unroll
    for (int i = 0; i < 4; i++)
#pragma unroll
        for (int j = 0; j < 4; j++)
#pragma unroll
            for (int e = 0; e < 4; e++) acc[i][j][e] = 0.f;

    for (int c = 0; c < NC; c++) {
        const int s = c % 3;
        const int rem = NC - 1 - c;
        if (rem >= 2) { CP_WAIT(2); } else if (rem == 1) { CP_WAIT(1); } else { CP_WAIT(0); }
        __syncthreads();

        const float* aB = sg + s * (GSTG / 4);
        const float* bB = aB + GMATF;

#pragma unroll
        for (int k0 = 0; k0 < 32; k0 += 8) {
            uint32_t a[4][4];
#pragma unroll
            for (int i = 0; i < 4; i++) {
                const int r = wm * 64 + i * 16 + lr;
                a[i][0] = __float_as_uint(aB[r * GLDS + k0 + lc]);
                a[i][1] = __float_as_uint(aB[(r + 8) * GLDS + k0 + lc]);
                a[i][2] = __float_as_uint(aB[r * GLDS + k0 + lc + 4]);
                a[i][3] = __float_as_uint(aB[(r + 8) * GLDS + k0 + lc + 4]);
            }
#pragma unroll
            for (int j = 0; j < 4; j++) {
                const int n = wn * 32 + j * 8 + lr;
                uint32_t bf[2] = { __float_as_uint(bB[n * GLDS + k0 + lc]),
                                   __float_as_uint(bB[n * GLDS + k0 + lc + 4]) };
#pragma unroll
                for (int i = 0; i < 4; i++)
                    mma_tf32(acc[i][j], a[i], bf);
            }
        }

        __syncthreads();
        if (c + 3 < NC) fill(s, c + 3);
    }

    // Epilogue: fragment -> global (float2)
    const int fc = lc << 1;
#pragma unroll
    for (int i = 0; i < 4; i++) {
#pragma unroll
        for (int j = 0; j < 4; j++) {
            const int n = bn + wn * 32 + j * 8 + fc;
#pragma unroll
            for (int half = 0; half < 2; half++) {
                const int m = bm + wm * 64 + i * 16 + lr + half * 8;
                float2 v = make_float2(acc[i][j][half * 2], acc[i][j][half * 2 + 1]);
                if (REMAP == 0) {
                    v.x = tf32r(v.x); v.y = tf32r(v.y);   // flash consumes as tf32
                    const int q = n >> 10, h = (n >> 6) & 15, kd = n & 63;
                    const int b = m >> 11, s2 = m & 2047;
                    *(float2*)&g_qkv[((((size_t)q * Bn + b) * Hn + h) * Sn + s2) * DKn + kd] = v;
                } else {
                    *(float2*)&C[(size_t)m * N + n] = v;
                }
            }
        }
    }
}

// ---------------------------------------------------------------------------
// Causal flash attention on tf32 mma.sync.
// CTA = (b, h, 128-row q tile); 8 warps, each owns 16 full S rows ->
// warp-local softmax. K tiles of 64. V transposed in smem (B operand).
// P acc-layout -> A-fragment-layout via quad shuffles (no smem staging).
// ---------------------------------------------------------------------------
#define FQL 68
#define F_SMEM ((128 + 64 + 64) * FQL * 4)   // Qs + Ks + Vt = 69632

__global__ void __launch_bounds__(256, 2) flash_tf32()
{
    extern __shared__ float smf[];
    float* Qs = smf;                    // [128][FQL]  (pre-scaled by 1/8)
    float* Ks = smf + 128 * FQL;        // [64][FQL]   natural [s][k]
    float* Vt = smf + 192 * FQL;        // [64][FQL]   transposed [d][s]

    const int qt = (Sn / 128 - 1) - blockIdx.x;   // largest workload first
    const int h = blockIdx.y, b = blockIdx.z;
    const int tid = threadIdx.x;
    const int lane = tid & 31, wid = tid >> 5;
    const int lr = lane >> 2, lc = lane & 3;

    const size_t headoff = (((size_t)b * Hn + h) * Sn) * DKn;
    const size_t plane = (size_t)Bn * Hn * Sn * DKn;
    const float* Qg = g_qkv + headoff;
    const float* Kg = g_qkv + plane + headoff;
    const float* Vg = g_qkv + 2 * plane + headoff;
    const uint32_t sbK = smem_u32(Ks);

    // Q tile: 128x64 floats, scaled by 1/8 (exact, preserves tf32-ness)
#pragma unroll
    for (int u = 0; u < 8; u++) {
        const int idx = tid + u * 256;
        const int r = idx >> 4, c = (idx & 15) << 2;
        float4 q = *(const float4*)(Qg + (size_t)(qt * 128 + r) * DKn + c);
        q.x *= 0.125f; q.y *= 0.125f; q.z *= 0.125f; q.w *= 0.125f;
        *(float4*)(Qs + r * FQL + c) = q;
    }

    float oacc[8][4];
#pragma unroll
    for (int j = 0; j < 8; j++)
#pragma unroll
        for (int e = 0; e < 4; e++) oacc[j][e] = 0.f;
    float m0 = -1e30f, m1 = -1e30f, l0 = 0.f, l1 = 0.f;

    const int KT = 2 * qt + 2;
    for (int kt = 0; kt < KT; kt++) {
        __syncthreads();   // prev iter done with Ks/Vt; Q visible on iter 0
#pragma unroll
        for (int u = 0; u < 4; u++) {
            const int idx = tid + u * 256;            // 0..1023
            const int r = idx >> 4, c = (idx & 15) << 2;
            cp16(sbK + (uint32_t)(r * FQL + c) * 4,
                 Kg + (size_t)(kt * 64 + r) * DKn + c);
            const float4 v = *(const float4*)(Vg + (size_t)(kt * 64 + r) * DKn + c);
            Vt[(c + 0) * FQL + r] = v.x;
            Vt[(c + 1) * FQL + r] = v.y;
            Vt[(c + 2) * FQL + r] = v.z;
            Vt[(c + 3) * FQL + r] = v.w;
        }
        CP_COMMIT(); CP_WAIT(0);
        __syncthreads();

        // S = Q K^T  (warp rows: 16*wid .. +16, all 64 cols)
        float sacc[8][4];
#pragma unroll
        for (int j = 0; j < 8; j++)
#pragma unroll
            for (int e = 0; e < 4; e++) sacc[j][e] = 0.f;

#pragma unroll
        for (int k0 = 0; k0 < 64; k0 += 8) {
            uint32_t a[4];
            const int r = wid * 16 + lr;
            a[0] = __float_as_uint(Qs[r * FQL + k0 + lc]);
            a[1] = __float_as_uint(Qs[(r + 8) * FQL + k0 + lc]);
            a[2] = __float_as_uint(Qs[r * FQL + k0 + lc + 4]);
            a[3] = __float_as_uint(Qs[(r + 8) * FQL + k0 + lc + 4]);
#pragma unroll
            for (int j = 0; j < 8; j++) {
                const int n = j * 8 + lr;
                uint32_t bf[2] = { __float_as_uint(Ks[n * FQL + k0 + lc]),
                                   __float_as_uint(Ks[n * FQL + k0 + lc + 4]) };
                mma_tf32(sacc[j], a, bf);
            }
        }

        // Causal mask (only the last two k-tiles can intersect the diagonal)
        if (kt * 64 + 63 > qt * 128) {
            const int qr0 = qt * 128 + wid * 16 + lr;
#pragma unroll
            for (int j = 0; j < 8; j++) {
                const int kc = kt * 64 + j * 8 + 2 * lc;
                if (kc     > qr0)     sacc[j][0] = -1e30f;
                if (kc + 1 > qr0)     sacc[j][1] = -1e30f;
                if (kc     > qr0 + 8) sacc[j][2] = -1e30f;
                if (kc + 1 > qr0 + 8) sacc[j][3] = -1e30f;
            }
        }

        // Warp-local online softmax (rows r0 = wid*16+lr, r1 = +8)
        float pm0 = -1e30f, pm1 = -1e30f;
#pragma unroll
        for (int j = 0; j < 8; j++) {
            pm0 = fmaxf(pm0, fmaxf(sacc[j][0], sacc[j][1]));
            pm1 = fmaxf(pm1, fmaxf(sacc[j][2], sacc[j][3]));
        }
        pm0 = fmaxf(pm0, __shfl_xor_sync(0xffffffffu, pm0, 1));
        pm0 = fmaxf(pm0, __shfl_xor_sync(0xffffffffu, pm0, 2));
        pm1 = fmaxf(pm1, __shfl_xor_sync(0xffffffffu, pm1, 1));
        pm1 = fmaxf(pm1, __shfl_xor_sync(0xffffffffu, pm1, 2));
        const float nm0 = fmaxf(m0, pm0), nm1 = fmaxf(m1, pm1);

        float sum0 = 0.f, sum1 = 0.f;
#pragma unroll
        for (int j = 0; j < 8; j++) {
            sacc[j][0] = __expf(sacc[j][0] - nm0);
            sacc[j][1] = __expf(sacc[j][1] - nm0);
            sacc[j][2] = __expf(sacc[j][2] - nm1);
            sacc[j][3] = __expf(sacc[j][3] - nm1);
            sum0 += sacc[j][0] + sacc[j][1];
            sum1 += sacc[j][2] + sacc[j][3];
        }
        sum0 += __shfl_xor_sync(0xffffffffu, sum0, 1);
        sum0 += __shfl_xor_sync(0xffffffffu, sum0, 2);
        sum1 += __shfl_xor_sync(0xffffffffu, sum1, 1);
        sum1 += __shfl_xor_sync(0xffffffffu, sum1, 2);

        const float al0 = __expf(m0 - nm0), al1 = __expf(m1 - nm1);
        l0 = l0 * al0 + sum0; l1 = l1 * al1 + sum1;
        m0 = nm0; m1 = nm1;
#pragma unroll
        for (int j = 0; j < 8; j++) {
            oacc[j][0] *= al0; oacc[j][1] *= al0;
            oacc[j][2] *= al1; oacc[j][3] *= al1;
        }

        // O += P V  (P acc-layout -> A-fragment via quad shuffles)
        const int srcA = (lane & ~3) | (lc >> 1);
        const int srcB = srcA + 2;
#pragma unroll
        for (int jk = 0; jk < 8; jk++) {
            const uint32_t p0 = __float_as_uint(tf32r(sacc[jk][0]));
            const uint32_t p1 = __float_as_uint(tf32r(sacc[jk][1]));
            const uint32_t p2 = __float_as_uint(tf32r(sacc[jk][2]));
            const uint32_t p3 = __float_as_uint(tf32r(sacc[jk][3]));
            uint32_t a[4], x0, x1;
            x0 = __shfl_sync(0xffffffffu, p0, srcA);
            x1 = __shfl_sync(0xffffffffu, p1, srcA);
            a[0] = (lc & 1) ? x1 : x0;
            x0 = __shfl_sync(0xffffffffu, p2, srcA);
            x1 = __shfl_sync(0xffffffffu, p3, srcA);
            a[1] = (lc & 1) ? x1 : x0;
            x0 = __shfl_sync(0xffffffffu, p0, srcB);
            x1 = __shfl_sync(0xffffffffu, p1, srcB);
            a[2] = (lc & 1) ? x1 : x0;
            x0 = __shfl_sync(0xffffffffu, p2, srcB);
            x1 = __shfl_sync(0xffffffffu, p3, srcB);
            a[3] = (lc & 1) ? x1 : x0;

            const int kk = jk * 8;
#pragma unroll
            for (int j2 = 0; j2 < 8; j2++) {
                const int n = j2 * 8 + lr;
                uint32_t bf[2] = { __float_as_uint(Vt[n * FQL + kk + lc]),
                                   __float_as_uint(Vt[n * FQL + kk + lc + 4]) };
                mma_tf32(oacc[j2], a, bf);
            }
        }
    }

    // Epilogue: normalize, rna (feeds out-proj as tf32), write [b][s][h*64+d]
    const float inv0 = 1.f / l0, inv1 = 1.f / l1;
    const int r0 = qt * 128 + wid * 16 + lr;
#pragma unroll
    for (int j2 = 0; j2 < 8; j2++) {
        const int col = h * 64 + j2 * 8 + 2 * lc;
        *(float2*)&g_attn[((size_t)b * Sn + r0) * Dn + col] =
            make_float2(tf32r(oacc[j2][0] * inv0), tf32r(oacc[j2][1] * inv0));
        *(float2*)&g_attn[((size_t)b * Sn + r0 + 8) * Dn + col] =
            make_float2(tf32r(oacc[j2][2] * inv1), tf32r(oacc[j2][3] * inv1));
    }
}

// ---------------------------------------------------------------------------

extern "C" void kernel_launch(void* const* d_in, const int* in_sizes, int n_in,
                              void* d_out, int out_size)
{
    const float* x     = (const float*)d_in[0];  // [B,S,D]
    const float* w_qkv = (const float*)d_in[1];  // [3,H,DK,D]
    const float* w_o   = (const float*)d_in[2];  // [D,D]
    float* out = (float*)d_out;                  // [B,S,D]

    const int M = Bn * Sn;   // 8192

    (void)cudaFuncSetAttribute(flash_tf32,
                               cudaFuncAttributeMaxDynamicSharedMemorySize, F_SMEM);
    (void)cudaFuncSetAttribute(gemm_tf32<0>,
                               cudaFuncAttributeMaxDynamicSharedMemorySize, G_SMEM);
    (void)cudaFuncSetAttribute(gemm_tf32<1>,
                               cudaFuncAttributeMaxDynamicSharedMemorySize, G_SMEM);

    float *xt, *wt, *wot, *attn;
    (void)cudaGetSymbolAddress((void**)&xt, g_xt);
    (void)cudaGetSymbolAddress((void**)&wt, g_wt);
    (void)cudaGetSymbolAddress((void**)&wot, g_wot);
    (void)cudaGetSymbolAddress((void**)&attn, g_attn);

    // 0) rna(tf32) pre-pass on inputs
    {
        int n4 = M * Dn / 4;
        cvt_kernel<<<(n4 + 255) / 256, 256>>>((const float4*)x, (float4*)xt, n4);
        n4 = 3 * Hn * DKn * Dn / 4;
        cvt_kernel<<<(n4 + 255) / 256, 256>>>((const float4*)w_qkv, (float4*)wt, n4);
        n4 = Dn * Dn / 4;
        cvt_kernel<<<(n4 + 255) / 256, 256>>>((const float4*)w_o, (float4*)wot, n4);
    }

    // 1) QKV projection (tf32 mma) -> g_qkv
    {
        dim3 grid(3 * Hn * DKn / 128, M / 128);  // (24, 64)
        gemm_tf32<0><<<grid, 256, G_SMEM>>>(xt, wt, nullptr, M, 3 * Hn * DKn, Dn);
    }

    // 2) Causal flash attention (tf32 mma) -> g_attn
    {
        dim3 grid(Sn / 128, Hn, Bn);  // (16, 16, 4)
        flash_tf32<<<grid, 256, F_SMEM>>>();
    }

    // 3) Output projection (tf32 mma) -> out
    {
        dim3 grid(Dn / 128, M / 128);  // (8, 64)
        gemm_tf32<1><<<grid, 256, G_SMEM>>>(attn, wot, out, M, Dn, Dn);
    }
}

// round 7
// speedup vs baseline: 3.4631x; 1.1037x over previous
#include <cuda_runtime.h>
#include <cstdint>
#include <cstddef>
#include <math.h>

#define Bn 4
#define Sn 2048
#define Dn 1024
#define Hn 16
#define DKn 64

// ---------------------------------------------------------------------------
// Scratch (alloc-free rule: __device__ globals)
// ---------------------------------------------------------------------------
__device__ float g_qkv[(size_t)3 * Bn * Hn * Sn * DKn];   // [q][b][h][s][k], tf32-valued
__device__ float g_attn[(size_t)Bn * Sn * Dn];            // [b][s][h*64+d], tf32-valued
__device__ float g_xt[(size_t)Bn * Sn * Dn];              // rna(x)
__device__ float g_wt[(size_t)3 * Hn * DKn * Dn];         // rna(w_qkv)
__device__ float g_wot[(size_t)Dn * Dn];                  // rna(w_o)

// ---------------------------------------------------------------------------
// PTX helpers (sm_100 baseline)
// ---------------------------------------------------------------------------
__device__ __forceinline__ uint32_t smem_u32(const void* p) {
    uint32_t a;
    asm("{ .reg .u64 t; cvta.to.shared.u64 t, %1; cvt.u32.u64 %0, t; }"
        : "=r"(a) : "l"(p));
    return a;
}

__device__ __forceinline__ void cp16(uint32_t dst, const void* src) {
    asm volatile("cp.async.cg.shared.global [%0], [%1], 16;"
                 :: "r"(dst), "l"(src));
}
#define CP_COMMIT() asm volatile("cp.async.commit_group;" ::: "memory")
#define CP_WAIT(n)  asm volatile("cp.async.wait_group %0;" :: "n"(n) : "memory")

__device__ __forceinline__ float tf32r(float x) {
    uint32_t u;
    asm("cvt.rna.tf32.f32 %0, %1;" : "=r"(u) : "f"(x));
    return __uint_as_float(u);
}

__device__ __forceinline__ void mma_tf32(float* d, const uint32_t* a, const uint32_t* b) {
    asm volatile("mma.sync.aligned.m16n8k8.row.col.f32.tf32.tf32.f32 "
                 "{%0,%1,%2,%3}, {%4,%5,%6,%7}, {%8,%9}, {%0,%1,%2,%3};"
                 : "+f"(d[0]), "+f"(d[1]), "+f"(d[2]), "+f"(d[3])
                 : "r"(a[0]), "r"(a[1]), "r"(a[2]), "r"(a[3]), "r"(b[0]), "r"(b[1]));
}

// ---------------------------------------------------------------------------
// Elementwise rna(tf32) pre-pass
// ---------------------------------------------------------------------------
__global__ void __launch_bounds__(256) cvt_kernel(
    const float4* __restrict__ in, float4* __restrict__ outp, int n4)
{
    int i = blockIdx.x * 256 + threadIdx.x;
    if (i >= n4) return;
    float4 v = in[i];
    v.x = tf32r(v.x); v.y = tf32r(v.y); v.z = tf32r(v.z); v.w = tf32r(v.w);
    outp[i] = v;
}

// ---------------------------------------------------------------------------
// tf32 GEMM: C[M,N] = A[M,K] * B[N,K]^T, fp32 accumulate.   (unchanged R6)
// ---------------------------------------------------------------------------
#define GLDS  36
#define GMATF (128 * GLDS)
#define GSTG  (2 * GMATF * 4)
#define G_SMEM (3 * GSTG)

template <int REMAP>
__global__ void __launch_bounds__(256, 2) gemm_tf32(
    const float* __restrict__ A, const float* __restrict__ Bm,
    float* __restrict__ C, int M, int N, int K)
{
    extern __shared__ float sg[];
    const uint32_t sb = smem_u32(sg);
    const int tid = threadIdx.x, lane = tid & 31, wid = tid >> 5;
    const int wm = wid >> 2, wn = wid & 3;
    const int lr = lane >> 2, lc = lane & 3;
    const int bm = blockIdx.y * 128, bn = blockIdx.x * 128;
    const int NC = K >> 5;

    const char* gA = (const char*)(A + (size_t)bm * K);
    const char* gB = (const char*)(Bm + (size_t)bn * K);

    auto fill = [&](int s, int c) {
        const uint32_t base = sb + s * GSTG;
        const int kof = c * 32;
#pragma unroll
        for (int u = 0; u < 4; u++) {
            const int ch = tid + u * 256;
            const int row = ch >> 3, col = (ch & 7) << 2;
            cp16(base + (uint32_t)(row * GLDS + col) * 4,
                 gA + ((size_t)row * K + kof + col) * 4);
            cp16(base + (uint32_t)GMATF * 4 + (uint32_t)(row * GLDS + col) * 4,
                 gB + ((size_t)row * K + kof + col) * 4);
        }
        CP_COMMIT();
    };

    fill(0, 0);
    if (NC > 1) fill(1, 1);
    if (NC > 2) fill(2, 2);

    float acc[4][4][4];
#pragma unroll
    for (int i = 0; i < 4; i++)
#pragma unroll
        for (int j = 0; j < 4; j++)
#pragma unroll
            for (int e = 0; e < 4; e++) acc[i][j][e] = 0.f;

    for (int c = 0; c < NC; c++) {
        const int s = c % 3;
        const int rem = NC - 1 - c;
        if (rem >= 2) { CP_WAIT(2); } else if (rem == 1) { CP_WAIT(1); } else { CP_WAIT(0); }
        __syncthreads();

        const float* aB = sg + s * (GSTG / 4);
        const float* bB = aB + GMATF;

#pragma unroll
        for (int k0 = 0; k0 < 32; k0 += 8) {
            uint32_t a[4][4];
#pragma unroll
            for (int i = 0; i < 4; i++) {
                const int r = wm * 64 + i * 16 + lr;
                a[i][0] = __float_as_uint(aB[r * GLDS + k0 + lc]);
                a[i][1] = __float_as_uint(aB[(r + 8) * GLDS + k0 + lc]);
                a[i][2] = __float_as_uint(aB[r * GLDS + k0 + lc + 4]);
                a[i][3] = __float_as_uint(aB[(r + 8) * GLDS + k0 + lc + 4]);
            }
#pragma unroll
            for (int j = 0; j < 4; j++) {
                const int n = wn * 32 + j * 8 + lr;
                uint32_t bf[2] = { __float_as_uint(bB[n * GLDS + k0 + lc]),
                                   __float_as_uint(bB[n * GLDS + k0 + lc + 4]) };
#pragma unroll
                for (int i = 0; i < 4; i++)
                    mma_tf32(acc[i][j], a[i], bf);
            }
        }

        __syncthreads();
        if (c + 3 < NC) fill(s, c + 3);
    }

    const int fc = lc << 1;
#pragma unroll
    for (int i = 0; i < 4; i++) {
#pragma unroll
        for (int j = 0; j < 4; j++) {
            const int n = bn + wn * 32 + j * 8 + fc;
#pragma unroll
            for (int half = 0; half < 2; half++) {
                const int m = bm + wm * 64 + i * 16 + lr + half * 8;
                float2 v = make_float2(acc[i][j][half * 2], acc[i][j][half * 2 + 1]);
                if (REMAP == 0) {
                    v.x = tf32r(v.x); v.y = tf32r(v.y);
                    const int q = n >> 10, h = (n >> 6) & 15, kd = n & 63;
                    const int b = m >> 11, s2 = m & 2047;
                    *(float2*)&g_qkv[((((size_t)q * Bn + b) * Hn + h) * Sn + s2) * DKn + kd] = v;
                } else {
                    *(float2*)&C[(size_t)m * N + n] = v;
                }
            }
        }
    }
}

// ---------------------------------------------------------------------------
// Causal flash attention on tf32 mma.sync.
// CTA = (b, h, 128-row q tile); 8 warps each own 16 S rows (warp-local softmax).
// NEW: double-buffered cp.async K+V stages; V kept natural [s][d] with stride
// 72 (bank = 8*lc+lr, conflict-free) and consumed directly as the B operand —
// no transpose pass, no blocking loads in the mainloop.
// ---------------------------------------------------------------------------
#define FQL 68                          // Q/K stride (bank = 4*lr+lc)
#define FVL 72                          // V stride  (bank = 8*lc+lr)
#define FKBYTES (64 * FQL * 4)          // 17408
#define FVBYTES (64 * FVL * 4)          // 18432
#define FSTG (FKBYTES + FVBYTES)        // 35840
#define F_SMEM (128 * FQL * 4 + 2 * FSTG)  // 106496

__global__ void __launch_bounds__(256, 2) flash_tf32()
{
    extern __shared__ float smf[];
    float* Qs = smf;                          // [128][FQL], pre-scaled by 1/8
    const uint32_t sbKV = smem_u32(smf + 128 * FQL);

    const int qt = (Sn / 128 - 1) - blockIdx.x;   // largest workload first
    const int h = blockIdx.y, b = blockIdx.z;
    const int tid = threadIdx.x;
    const int lane = tid & 31, wid = tid >> 5;
    const int lr = lane >> 2, lc = lane & 3;

    const size_t headoff = (((size_t)b * Hn + h) * Sn) * DKn;
    const size_t plane = (size_t)Bn * Hn * Sn * DKn;
    const float* Qg = g_qkv + headoff;
    const float* Kg = g_qkv + plane + headoff;
    const float* Vg = g_qkv + 2 * plane + headoff;

    // Fill stage s with K/V tile kt: 64 rows x 256B each, all cp.async.
    auto fillKV = [&](int s, int kt) {
        const uint32_t base = sbKV + s * FSTG;
#pragma unroll
        for (int u = 0; u < 4; u++) {
            const int ch = tid + u * 256;             // 0..1023
            const int r = ch >> 4, c = (ch & 15) << 2;
            const float* src = Kg + (size_t)(kt * 64 + r) * DKn + c;
            cp16(base + (uint32_t)(r * FQL + c) * 4, src);
            cp16(base + FKBYTES + (uint32_t)(r * FVL + c) * 4, src + plane);
        }
        CP_COMMIT();
    };

    const int KT = 2 * qt + 2;
    fillKV(0, 0);

    // Q tile load overlaps with the first cp.async stage.
#pragma unroll
    for (int u = 0; u < 8; u++) {
        const int idx = tid + u * 256;
        const int r = idx >> 4, c = (idx & 15) << 2;
        float4 q = *(const float4*)(Qg + (size_t)(qt * 128 + r) * DKn + c);
        q.x *= 0.125f; q.y *= 0.125f; q.z *= 0.125f; q.w *= 0.125f;
        *(float4*)(Qs + r * FQL + c) = q;
    }

    float oacc[8][4];
#pragma unroll
    for (int j = 0; j < 8; j++)
#pragma unroll
        for (int e = 0; e < 4; e++) oacc[j][e] = 0.f;
    float m0 = -1e30f, m1 = -1e30f, l0 = 0.f, l1 = 0.f;

    for (int kt = 0; kt < KT; kt++) {
        const int s = kt & 1;
        // Prefetch next tile into the other stage (safe: consumed at kt-1,
        // all warps past it via the trailing __syncthreads()).
        if (kt + 1 < KT) { fillKV(s ^ 1, kt + 1); CP_WAIT(1); }
        else             { CP_WAIT(0); }
        __syncthreads();

        const float* Ks = smf + 128 * FQL + s * (FSTG / 4);
        const float* Vs = Ks + FKBYTES / 4;

        // S = Q K^T  (warp rows 16*wid..+16, all 64 cols)
        float sacc[8][4];
#pragma unroll
        for (int j = 0; j < 8; j++)
#pragma unroll
            for (int e = 0; e < 4; e++) sacc[j][e] = 0.f;

#pragma unroll
        for (int k0 = 0; k0 < 64; k0 += 8) {
            uint32_t a[4];
            const int r = wid * 16 + lr;
            a[0] = __float_as_uint(Qs[r * FQL + k0 + lc]);
            a[1] = __float_as_uint(Qs[(r + 8) * FQL + k0 + lc]);
            a[2] = __float_as_uint(Qs[r * FQL + k0 + lc + 4]);
            a[3] = __float_as_uint(Qs[(r + 8) * FQL + k0 + lc + 4]);
#pragma unroll
            for (int j = 0; j < 8; j++) {
                const int n = j * 8 + lr;
                uint32_t bf[2] = { __float_as_uint(Ks[n * FQL + k0 + lc]),
                                   __float_as_uint(Ks[n * FQL + k0 + lc + 4]) };
                mma_tf32(sacc[j], a, bf);
            }
        }

        // Causal mask (only tiles touching the diagonal)
        if (kt * 64 + 63 > qt * 128) {
            const int qr0 = qt * 128 + wid * 16 + lr;
#pragma unroll
            for (int j = 0; j < 8; j++) {
                const int kc = kt * 64 + j * 8 + 2 * lc;
                if (kc     > qr0)     sacc[j][0] = -1e30f;
                if (kc + 1 > qr0)     sacc[j][1] = -1e30f;
                if (kc     > qr0 + 8) sacc[j][2] = -1e30f;
                if (kc + 1 > qr0 + 8) sacc[j][3] = -1e30f;
            }
        }

        // Warp-local online softmax (rows r0 = wid*16+lr, r1 = +8)
        float pm0 = -1e30f, pm1 = -1e30f;
#pragma unroll
        for (int j = 0; j < 8; j++) {
            pm0 = fmaxf(pm0, fmaxf(sacc[j][0], sacc[j][1]));
            pm1 = fmaxf(pm1, fmaxf(sacc[j][2], sacc[j][3]));
        }
        pm0 = fmaxf(pm0, __shfl_xor_sync(0xffffffffu, pm0, 1));
        pm0 = fmaxf(pm0, __shfl_xor_sync(0xffffffffu, pm0, 2));
        pm1 = fmaxf(pm1, __shfl_xor_sync(0xffffffffu, pm1, 1));
        pm1 = fmaxf(pm1, __shfl_xor_sync(0xffffffffu, pm1, 2));
        const float nm0 = fmaxf(m0, pm0), nm1 = fmaxf(m1, pm1);

        float sum0 = 0.f, sum1 = 0.f;
#pragma unroll
        for (int j = 0; j < 8; j++) {
            sacc[j][0] = __expf(sacc[j][0] - nm0);
            sacc[j][1] = __expf(sacc[j][1] - nm0);
            sacc[j][2] = __expf(sacc[j][2] - nm1);
            sacc[j][3] = __expf(sacc[j][3] - nm1);
            sum0 += sacc[j][0] + sacc[j][1];
            sum1 += sacc[j][2] + sacc[j][3];
        }
        sum0 += __shfl_xor_sync(0xffffffffu, sum0, 1);
        sum0 += __shfl_xor_sync(0xffffffffu, sum0, 2);
        sum1 += __shfl_xor_sync(0xffffffffu, sum1, 1);
        sum1 += __shfl_xor_sync(0xffffffffu, sum1, 2);

        const float al0 = __expf(m0 - nm0), al1 = __expf(m1 - nm1);
        l0 = l0 * al0 + sum0; l1 = l1 * al1 + sum1;
        m0 = nm0; m1 = nm1;
#pragma unroll
        for (int j = 0; j < 8; j++) {
            oacc[j][0] *= al0; oacc[j][1] *= al0;
            oacc[j][2] *= al1; oacc[j][3] *= al1;
        }

        // O += P V  (P acc-layout -> A-fragment via quad shuffles;
        //            B fragment read directly from natural Vs[s][d])
        const int srcA = (lane & ~3) | (lc >> 1);
        const int srcB = srcA + 2;
#pragma unroll
        for (int jk = 0; jk < 8; jk++) {
            const uint32_t p0 = __float_as_uint(tf32r(sacc[jk][0]));
            const uint32_t p1 = __float_as_uint(tf32r(sacc[jk][1]));
            const uint32_t p2 = __float_as_uint(tf32r(sacc[jk][2]));
            const uint32_t p3 = __float_as_uint(tf32r(sacc[jk][3]));
            uint32_t a[4], x0, x1;
            x0 = __shfl_sync(0xffffffffu, p0, srcA);
            x1 = __shfl_sync(0xffffffffu, p1, srcA);
            a[0] = (lc & 1) ? x1 : x0;
            x0 = __shfl_sync(0xffffffffu, p2, srcA);
            x1 = __shfl_sync(0xffffffffu, p3, srcA);
            a[1] = (lc & 1) ? x1 : x0;
            x0 = __shfl_sync(0xffffffffu, p0, srcB);
            x1 = __shfl_sync(0xffffffffu, p1, srcB);
            a[2] = (lc & 1) ? x1 : x0;
            x0 = __shfl_sync(0xffffffffu, p2, srcB);
            x1 = __shfl_sync(0xffffffffu, p3, srcB);
            a[3] = (lc & 1) ? x1 : x0;

            const int kk = jk * 8;
#pragma unroll
            for (int j2 = 0; j2 < 8; j2++) {
                const int n = j2 * 8 + lr;
                uint32_t bf[2] = { __float_as_uint(Vs[(kk + lc) * FVL + n]),
                                   __float_as_uint(Vs[(kk + lc + 4) * FVL + n]) };
                mma_tf32(oacc[j2], a, bf);
            }
        }
        __syncthreads();   // all reads of stage s done before refill next iter
    }

    // Epilogue: normalize, rna (feeds out-proj as tf32), write [b][s][h*64+d]
    const float inv0 = 1.f / l0, inv1 = 1.f / l1;
    const int r0 = qt * 128 + wid * 16 + lr;
#pragma unroll
    for (int j2 = 0; j2 < 8; j2++) {
        const int col = h * 64 + j2 * 8 + 2 * lc;
        *(float2*)&g_attn[((size_t)b * Sn + r0) * Dn + col] =
            make_float2(tf32r(oacc[j2][0] * inv0), tf32r(oacc[j2][1] * inv0));
        *(float2*)&g_attn[((size_t)b * Sn + r0 + 8) * Dn + col] =
            make_float2(tf32r(oacc[j2][2] * inv1), tf32r(oacc[j2][3] * inv1));
    }
}

// ---------------------------------------------------------------------------

extern "C" void kernel_launch(void* const* d_in, const int* in_sizes, int n_in,
                              void* d_out, int out_size)
{
    const float* x     = (const float*)d_in[0];  // [B,S,D]
    const float* w_qkv = (const float*)d_in[1];  // [3,H,DK,D]
    const float* w_o   = (const float*)d_in[2];  // [D,D]
    float* out = (float*)d_out;                  // [B,S,D]

    const int M = Bn * Sn;   // 8192

    (void)cudaFuncSetAttribute(flash_tf32,
                               cudaFuncAttributeMaxDynamicSharedMemorySize, F_SMEM);
    (void)cudaFuncSetAttribute(gemm_tf32<0>,
                               cudaFuncAttributeMaxDynamicSharedMemorySize, G_SMEM);
    (void)cudaFuncSetAttribute(gemm_tf32<1>,
                               cudaFuncAttributeMaxDynamicSharedMemorySize, G_SMEM);

    float *xt, *wt, *wot, *attn;
    (void)cudaGetSymbolAddress((void**)&xt, g_xt);
    (void)cudaGetSymbolAddress((void**)&wt, g_wt);
    (void)cudaGetSymbolAddress((void**)&wot, g_wot);
    (void)cudaGetSymbolAddress((void**)&attn, g_attn);

    // 0) rna(tf32) pre-pass on inputs
    {
        int n4 = M * Dn / 4;
        cvt_kernel<<<(n4 + 255) / 256, 256>>>((const float4*)x, (float4*)xt, n4);
        n4 = 3 * Hn * DKn * Dn / 4;
        cvt_kernel<<<(n4 + 255) / 256, 256>>>((const float4*)w_qkv, (float4*)wt, n4);
        n4 = Dn * Dn / 4;
        cvt_kernel<<<(n4 + 255) / 256, 256>>>((const float4*)w_o, (float4*)wot, n4);
    }

    // 1) QKV projection (tf32 mma) -> g_qkv
    {
        dim3 grid(3 * Hn * DKn / 128, M / 128);  // (24, 64)
        gemm_tf32<0><<<grid, 256, G_SMEM>>>(xt, wt, nullptr, M, 3 * Hn * DKn, Dn);
    }

    // 2) Causal flash attention (tf32 mma) -> g_attn
    {
        dim3 grid(Sn / 128, Hn, Bn);  // (16, 16, 4)
        flash_tf32<<<grid, 256, F_SMEM>>>();
    }

    // 3) Output projection (tf32 mma) -> out
    {
        dim3 grid(Dn / 128, M / 128);  // (8, 64)
        gemm_tf32<1><<<grid, 256, G_SMEM>>>(attn, wot, out, M, Dn, Dn);
    }
}

// round 8
// speedup vs baseline: 3.6876x; 1.0648x over previous
#include <cuda_runtime.h>
#include <cstdint>
#include <cstddef>
#include <math.h>

#define Bn 4
#define Sn 2048
#define Dn 1024
#define Hn 16
#define DKn 64

// ---------------------------------------------------------------------------
// Scratch (alloc-free rule: __device__ globals)
// ---------------------------------------------------------------------------
__device__ float g_qkv[(size_t)3 * Bn * Hn * Sn * DKn];   // [q][b][h][s][k], tf32-valued
__device__ float g_attn[(size_t)Bn * Sn * Dn];            // [b][s][h*64+d], tf32-valued
__device__ float g_xt[(size_t)Bn * Sn * Dn];              // rna(x)
__device__ float g_wt[(size_t)3 * Hn * DKn * Dn];         // rna(w_qkv)
__device__ float g_wot[(size_t)Dn * Dn];                  // rna(w_o)

// ---------------------------------------------------------------------------
// PTX helpers (sm_100 baseline)
// ---------------------------------------------------------------------------
__device__ __forceinline__ uint32_t smem_u32(const void* p) {
    uint32_t a;
    asm("{ .reg .u64 t; cvta.to.shared.u64 t, %1; cvt.u32.u64 %0, t; }"
        : "=r"(a) : "l"(p));
    return a;
}

__device__ __forceinline__ void cp16(uint32_t dst, const void* src) {
    asm volatile("cp.async.cg.shared.global [%0], [%1], 16;"
                 :: "r"(dst), "l"(src));
}
#define CP_COMMIT() asm volatile("cp.async.commit_group;" ::: "memory")
#define CP_WAIT(n)  asm volatile("cp.async.wait_group %0;" :: "n"(n) : "memory")

__device__ __forceinline__ float tf32r(float x) {
    uint32_t u;
    asm("cvt.rna.tf32.f32 %0, %1;" : "=r"(u) : "f"(x));
    return __uint_as_float(u);
}

// ldmatrix on fp32 data viewed as b16 pairs: lane L receives row L/4,
// float-column L%4 of each 8x8-float matrix -> exact tf32 fragment layout.
__device__ __forceinline__ void ldsm4(uint32_t* r, uint32_t addr) {
    asm volatile("ldmatrix.sync.aligned.m8n8.x4.shared.b16 {%0,%1,%2,%3}, [%4];"
                 : "=r"(r[0]), "=r"(r[1]), "=r"(r[2]), "=r"(r[3]) : "r"(addr));
}

__device__ __forceinline__ void mma_tf32(float* d, const uint32_t* a, const uint32_t* b) {
    asm volatile("mma.sync.aligned.m16n8k8.row.col.f32.tf32.tf32.f32 "
                 "{%0,%1,%2,%3}, {%4,%5,%6,%7}, {%8,%9}, {%0,%1,%2,%3};"
                 : "+f"(d[0]), "+f"(d[1]), "+f"(d[2]), "+f"(d[3])
                 : "r"(a[0]), "r"(a[1]), "r"(a[2]), "r"(a[3]), "r"(b[0]), "r"(b[1]));
}

// ---------------------------------------------------------------------------
// Elementwise rna(tf32) pre-pass
// ---------------------------------------------------------------------------
__global__ void __launch_bounds__(256) cvt_kernel(
    const float4* __restrict__ in, float4* __restrict__ outp, int n4)
{
    int i = blockIdx.x * 256 + threadIdx.x;
    if (i >= n4) return;
    float4 v = in[i];
    v.x = tf32r(v.x); v.y = tf32r(v.y); v.z = tf32r(v.z); v.w = tf32r(v.w);
    outp[i] = v;
}

// ---------------------------------------------------------------------------
// tf32 GEMM: C[M,N] = A[M,K] * B[N,K]^T, fp32 accumulate.
// 128x128 CTA tile, BK=32, 8 warps (2x4), warp tile 64x32, 3-stage cp.async.
// Fragments via ldmatrix (6 loads : 16 mma per k8).
// ---------------------------------------------------------------------------
#define GLDS  36
#define GMATF (128 * GLDS)
#define GSTG  (2 * GMATF * 4)
#define G_SMEM (3 * GSTG)

template <int REMAP>
__global__ void __launch_bounds__(256, 2) gemm_tf32(
    const float* __restrict__ A, const float* __restrict__ Bm,
    float* __restrict__ C, int M, int N, int K)
{
    extern __shared__ float sg[];
    const uint32_t sb = smem_u32(sg);
    const int tid = threadIdx.x, lane = tid & 31, wid = tid >> 5;
    const int wm = wid >> 2, wn = wid & 3;
    const int lr = lane >> 2, lc = lane & 3;
    const int bm = blockIdx.y * 128, bn = blockIdx.x * 128;
    const int NC = K >> 5;

    const char* gA = (const char*)(A + (size_t)bm * K);
    const char* gB = (const char*)(Bm + (size_t)bn * K);

    auto fill = [&](int s, int c) {
        const uint32_t base = sb + s * GSTG;
        const int kof = c * 32;
#pragma unroll
        for (int u = 0; u < 4; u++) {
            const int ch = tid + u * 256;
            const int row = ch >> 3, col = (ch & 7) << 2;
            cp16(base + (uint32_t)(row * GLDS + col) * 4,
                 gA + ((size_t)row * K + kof + col) * 4);
            cp16(base + (uint32_t)GMATF * 4 + (uint32_t)(row * GLDS + col) * 4,
                 gB + ((size_t)row * K + kof + col) * 4);
        }
        CP_COMMIT();
    };

    fill(0, 0);
    if (NC > 1) fill(1, 1);
    if (NC > 2) fill(2, 2);

    float acc[4][4][4];
#pragma unroll
    for (int i = 0; i < 4; i++)
#pragma unroll
        for (int j = 0; j < 4; j++)
#pragma unroll
            for (int e = 0; e < 4; e++) acc[i][j][e] = 0.f;

    // ldmatrix lane addressing (float-element offsets)
    const uint32_t aOff = (uint32_t)((wm * 64 + (lane & 15)) * GLDS + ((lane >> 4) << 2)) * 4;
    const uint32_t bOff = (uint32_t)((wn * 32 + (((lane >> 4) & 1) << 3) + (lane & 7)) * GLDS
                                     + (((lane >> 3) & 1) << 2)) * 4;

    for (int c = 0; c < NC; c++) {
        const int s = c % 3;
        const int rem = NC - 1 - c;
        if (rem >= 2) { CP_WAIT(2); } else if (rem == 1) { CP_WAIT(1); } else { CP_WAIT(0); }
        __syncthreads();

        const uint32_t aB = sb + s * GSTG + aOff;
        const uint32_t bB = sb + s * GSTG + (uint32_t)GMATF * 4 + bOff;

#pragma unroll
        for (int k0 = 0; k0 < 32; k0 += 8) {
            uint32_t a[4][4], bq[2][4];
#pragma unroll
            for (int i = 0; i < 4; i++)
                ldsm4(a[i], aB + (uint32_t)(i * 16 * GLDS + k0) * 4);
#pragma unroll
            for (int jp = 0; jp < 2; jp++)
                ldsm4(bq[jp], bB + (uint32_t)(jp * 16 * GLDS + k0) * 4);
#pragma unroll
            for (int jp = 0; jp < 2; jp++)
#pragma unroll
                for (int i = 0; i < 4; i++) {
                    mma_tf32(acc[i][2 * jp],     a[i], &bq[jp][0]);
                    mma_tf32(acc[i][2 * jp + 1], a[i], &bq[jp][2]);
                }
        }

        __syncthreads();
        if (c + 3 < NC) fill(s, c + 3);
    }

    const int fc = lc << 1;
#pragma unroll
    for (int i = 0; i < 4; i++) {
#pragma unroll
        for (int j = 0; j < 4; j++) {
            const int n = bn + wn * 32 + j * 8 + fc;
#pragma unroll
            for (int half = 0; half < 2; half++) {
                const int m = bm + wm * 64 + i * 16 + lr + half * 8;
                float2 v = make_float2(acc[i][j][half * 2], acc[i][j][half * 2 + 1]);
                if (REMAP == 0) {
                    v.x = tf32r(v.x); v.y = tf32r(v.y);
                    const int q = n >> 10, h = (n >> 6) & 15, kd = n & 63;
                    const int b = m >> 11, s2 = m & 2047;
                    *(float2*)&g_qkv[((((size_t)q * Bn + b) * Hn + h) * Sn + s2) * DKn + kd] = v;
                } else {
                    *(float2*)&C[(size_t)m * N + n] = v;
                }
            }
        }
    }
}

// ---------------------------------------------------------------------------
// Causal flash attention on tf32 mma.sync.
// CTA = (b, h, 128-row q tile); 8 warps each own 16 S rows (warp-local softmax).
// Double-buffered cp.async K+V. S-loop fragments via ldmatrix (5 loads : 8 mma
// per k8); V consumed directly from natural [s][d] layout (stride 72).
// ---------------------------------------------------------------------------
#define FQL 68                          // Q/K stride (bank = 4*lr+lc)
#define FVL 72                          // V stride  (bank = 8*lc+lr)
#define FKBYTES (64 * FQL * 4)          // 17408
#define FVBYTES (64 * FVL * 4)          // 18432
#define FSTG (FKBYTES + FVBYTES)        // 35840
#define F_SMEM (128 * FQL * 4 + 2 * FSTG)  // 106496

__global__ void __launch_bounds__(256, 2) flash_tf32()
{
    extern __shared__ float smf[];
    float* Qs = smf;                          // [128][FQL], pre-scaled by 1/8
    const uint32_t sbQ  = smem_u32(smf);
    const uint32_t sbKV = sbQ + 128 * FQL * 4;

    const int qt = (Sn / 128 - 1) - blockIdx.x;   // largest workload first
    const int h = blockIdx.y, b = blockIdx.z;
    const int tid = threadIdx.x;
    const int lane = tid & 31, wid = tid >> 5;
    const int lr = lane >> 2, lc = lane & 3;

    const size_t headoff = (((size_t)b * Hn + h) * Sn) * DKn;
    const size_t plane = (size_t)Bn * Hn * Sn * DKn;
    const float* Qg = g_qkv + headoff;
    const float* Kg = g_qkv + plane + headoff;
    const float* Vg = g_qkv + 2 * plane + headoff;

    auto fillKV = [&](int s, int kt) {
        const uint32_t base = sbKV + s * FSTG;
#pragma unroll
        for (int u = 0; u < 4; u++) {
            const int ch = tid + u * 256;
            const int r = ch >> 4, c = (ch & 15) << 2;
            const float* src = Kg + (size_t)(kt * 64 + r) * DKn + c;
            cp16(base + (uint32_t)(r * FQL + c) * 4, src);
            cp16(base + FKBYTES + (uint32_t)(r * FVL + c) * 4, src + plane);
        }
        CP_COMMIT();
    };

    const int KT = 2 * qt + 2;
    fillKV(0, 0);

#pragma unroll
    for (int u = 0; u < 8; u++) {
        const int idx = tid + u * 256;
        const int r = idx >> 4, c = (idx & 15) << 2;
        float4 q = *(const float4*)(Qg + (size_t)(qt * 128 + r) * DKn + c);
        q.x *= 0.125f; q.y *= 0.125f; q.z *= 0.125f; q.w *= 0.125f;
        *(float4*)(Qs + r * FQL + c) = q;
    }

    float oacc[8][4];
#pragma unroll
    for (int j = 0; j < 8; j++)
#pragma unroll
        for (int e = 0; e < 4; e++) oacc[j][e] = 0.f;
    float m0 = -1e30f, m1 = -1e30f, l0 = 0.f, l1 = 0.f;

    // ldmatrix lane addressing
    const uint32_t qOff = sbQ +
        (uint32_t)((wid * 16 + (lane & 15)) * FQL + ((lane >> 4) << 2)) * 4;
    const uint32_t kOff =
        (uint32_t)(((((lane >> 4) & 1) << 3) + (lane & 7)) * FQL + (((lane >> 3) & 1) << 2)) * 4;

    for (int kt = 0; kt < KT; kt++) {
        const int s = kt & 1;
        if (kt + 1 < KT) { fillKV(s ^ 1, kt + 1); CP_WAIT(1); }
        else             { CP_WAIT(0); }
        __syncthreads();

        const uint32_t ksb = sbKV + s * FSTG;
        const float* Vs = smf + (ksb - sbQ + FKBYTES) / 4;

        // S = Q K^T
        float sacc[8][4];
#pragma unroll
        for (int j = 0; j < 8; j++)
#pragma unroll
            for (int e = 0; e < 4; e++) sacc[j][e] = 0.f;

#pragma unroll
        for (int k0 = 0; k0 < 64; k0 += 8) {
            uint32_t a[4];
            ldsm4(a, qOff + (uint32_t)k0 * 4);
#pragma unroll
            for (int jp = 0; jp < 4; jp++) {
                uint32_t kq[4];
                ldsm4(kq, ksb + kOff + (uint32_t)(jp * 16 * FQL + k0) * 4);
                mma_tf32(sacc[2 * jp],     a, &kq[0]);
                mma_tf32(sacc[2 * jp + 1], a, &kq[2]);
            }
        }

        // Causal mask (only tiles touching the diagonal)
        if (kt * 64 + 63 > qt * 128) {
            const int qr0 = qt * 128 + wid * 16 + lr;
#pragma unroll
            for (int j = 0; j < 8; j++) {
                const int kc = kt * 64 + j * 8 + 2 * lc;
                if (kc     > qr0)     sacc[j][0] = -1e30f;
                if (kc + 1 > qr0)     sacc[j][1] = -1e30f;
                if (kc     > qr0 + 8) sacc[j][2] = -1e30f;
                if (kc + 1 > qr0 + 8) sacc[j][3] = -1e30f;
            }
        }

        // Warp-local online softmax
        float pm0 = -1e30f, pm1 = -1e30f;
#pragma unroll
        for (int j = 0; j < 8; j++) {
            pm0 = fmaxf(pm0, fmaxf(sacc[j][0], sacc[j][1]));
            pm1 = fmaxf(pm1, fmaxf(sacc[j][2], sacc[j][3]));
        }
        pm0 = fmaxf(pm0, __shfl_xor_sync(0xffffffffu, pm0, 1));
        pm0 = fmaxf(pm0, __shfl_xor_sync(0xffffffffu, pm0, 2));
        pm1 = fmaxf(pm1, __shfl_xor_sync(0xffffffffu, pm1, 1));
        pm1 = fmaxf(pm1, __shfl_xor_sync(0xffffffffu, pm1, 2));
        const float nm0 = fmaxf(m0, pm0), nm1 = fmaxf(m1, pm1);

        float sum0 = 0.f, sum1 = 0.f;
#pragma unroll
        for (int j = 0; j < 8; j++) {
            sacc[j][0] = __expf(sacc[j][0] - nm0);
            sacc[j][1] = __expf(sacc[j][1] - nm0);
            sacc[j][2] = __expf(sacc[j][2] - nm1);
            sacc[j][3] = __expf(sacc[j][3] - nm1);
            sum0 += sacc[j][0] + sacc[j][1];
            sum1 += sacc[j][2] + sacc[j][3];
        }
        sum0 += __shfl_xor_sync(0xffffffffu, sum0, 1);
        sum0 += __shfl_xor_sync(0xffffffffu, sum0, 2);
        sum1 += __shfl_xor_sync(0xffffffffu, sum1, 1);
        sum1 += __shfl_xor_sync(0xffffffffu, sum1, 2);

        const float al0 = __expf(m0 - nm0), al1 = __expf(m1 - nm1);
        l0 = l0 * al0 + sum0; l1 = l1 * al1 + sum1;
        m0 = nm0; m1 = nm1;
#pragma unroll
        for (int j = 0; j < 8; j++) {
            oacc[j][0] *= al0; oacc[j][1] *= al0;
            oacc[j][2] *= al1; oacc[j][3] *= al1;
        }

        // O += P V  (P acc-layout -> A-fragment via quad shuffles;
        //            B fragment read directly from natural Vs[s][d])
        const int srcA = (lane & ~3) | (lc >> 1);
        const int srcB = srcA + 2;
#pragma unroll
        for (int jk = 0; jk < 8; jk++) {
            const uint32_t p0 = __float_as_uint(tf32r(sacc[jk][0]));
            const uint32_t p1 = __float_as_uint(tf32r(sacc[jk][1]));
            const uint32_t p2 = __float_as_uint(tf32r(sacc[jk][2]));
            const uint32_t p3 = __float_as_uint(tf32r(sacc[jk][3]));
            uint32_t a[4], x0, x1;
            x0 = __shfl_sync(0xffffffffu, p0, srcA);
            x1 = __shfl_sync(0xffffffffu, p1, srcA);
            a[0] = (lc & 1) ? x1 : x0;
            x0 = __shfl_sync(0xffffffffu, p2, srcA);
            x1 = __shfl_sync(0xffffffffu, p3, srcA);
            a[1] = (lc & 1) ? x1 : x0;
            x0 = __shfl_sync(0xffffffffu, p0, srcB);
            x1 = __shfl_sync(0xffffffffu, p1, srcB);
            a[2] = (lc & 1) ? x1 : x0;
            x0 = __shfl_sync(0xffffffffu, p2, srcB);
            x1 = __shfl_sync(0xffffffffu, p3, srcB);
            a[3] = (lc & 1) ? x1 : x0;

            const int kk = jk * 8;
#pragma unroll
            for (int j2 = 0; j2 < 8; j2++) {
                const int n = j2 * 8 + lr;
                uint32_t bf[2] = { __float_as_uint(Vs[(kk + lc) * FVL + n]),
                                   __float_as_uint(Vs[(kk + lc + 4) * FVL + n]) };
                mma_tf32(oacc[j2], a, bf);
            }
        }
        __syncthreads();
    }

    // Epilogue: normalize, rna (feeds out-proj as tf32), write [b][s][h*64+d]
    const float inv0 = 1.f / l0, inv1 = 1.f / l1;
    const int r0 = qt * 128 + wid * 16 + lr;
#pragma unroll
    for (int j2 = 0; j2 < 8; j2++) {
        const int col = h * 64 + j2 * 8 + 2 * lc;
        *(float2*)&g_attn[((size_t)b * Sn + r0) * Dn + col] =
            make_float2(tf32r(oacc[j2][0] * inv0), tf32r(oacc[j2][1] * inv0));
        *(float2*)&g_attn[((size_t)b * Sn + r0 + 8) * Dn + col] =
            make_float2(tf32r(oacc[j2][2] * inv1), tf32r(oacc[j2][3] * inv1));
    }
}

// ---------------------------------------------------------------------------

extern "C" void kernel_launch(void* const* d_in, const int* in_sizes, int n_in,
                              void* d_out, int out_size)
{
    const float* x     = (const float*)d_in[0];  // [B,S,D]
    const float* w_qkv = (const float*)d_in[1];  // [3,H,DK,D]
    const float* w_o   = (const float*)d_in[2];  // [D,D]
    float* out = (float*)d_out;                  // [B,S,D]

    const int M = Bn * Sn;   // 8192

    (void)cudaFuncSetAttribute(flash_tf32,
                               cudaFuncAttributeMaxDynamicSharedMemorySize, F_SMEM);
    (void)cudaFuncSetAttribute(gemm_tf32<0>,
                               cudaFuncAttributeMaxDynamicSharedMemorySize, G_SMEM);
    (void)cudaFuncSetAttribute(gemm_tf32<1>,
                               cudaFuncAttributeMaxDynamicSharedMemorySize, G_SMEM);

    float *xt, *wt, *wot, *attn;
    (void)cudaGetSymbolAddress((void**)&xt, g_xt);
    (void)cudaGetSymbolAddress((void**)&wt, g_wt);
    (void)cudaGetSymbolAddress((void**)&wot, g_wot);
    (void)cudaGetSymbolAddress((void**)&attn, g_attn);

    // 0) rna(tf32) pre-pass on inputs
    {
        int n4 = M * Dn / 4;
        cvt_kernel<<<(n4 + 255) / 256, 256>>>((const float4*)x, (float4*)xt, n4);
        n4 = 3 * Hn * DKn * Dn / 4;
        cvt_kernel<<<(n4 + 255) / 256, 256>>>((const float4*)w_qkv, (float4*)wt, n4);
        n4 = Dn * Dn / 4;
        cvt_kernel<<<(n4 + 255) / 256, 256>>>((const float4*)w_o, (float4*)wot, n4);
    }

    // 1) QKV projection (tf32 mma) -> g_qkv
    {
        dim3 grid(3 * Hn * DKn / 128, M / 128);  // (24, 64)
        gemm_tf32<0><<<grid, 256, G_SMEM>>>(xt, wt, nullptr, M, 3 * Hn * DKn, Dn);
    }

    // 2) Causal flash attention (tf32 mma) -> g_attn
    {
        dim3 grid(Sn / 128, Hn, Bn);  // (16, 16, 4)
        flash_tf32<<<grid, 256, F_SMEM>>>();
    }

    // 3) Output projection (tf32 mma) -> out
    {
        dim3 grid(Dn / 128, M / 128);  // (8, 64)
        gemm_tf32<1><<<grid, 256, G_SMEM>>>(attn, wot, out, M, Dn, Dn);
    }
}

// round 9
// speedup vs baseline: 3.7497x; 1.0168x over previous
#include <cuda_runtime.h>
#include <cstdint>
#include <cstddef>
#include <math.h>

#define Bn 4
#define Sn 2048
#define Dn 1024
#define Hn 16
#define DKn 64

// ---------------------------------------------------------------------------
// Scratch (alloc-free rule: __device__ globals)
// ---------------------------------------------------------------------------
__device__ float g_qkv[(size_t)3 * Bn * Hn * Sn * DKn];   // [q][b][h][s][k], tf32-valued
__device__ float g_attn[(size_t)Bn * Sn * Dn];            // [b][s][h*64+d], tf32-valued
__device__ float g_xt[(size_t)Bn * Sn * Dn];              // rna(x)
__device__ float g_wt[(size_t)3 * Hn * DKn * Dn];         // rna(w_qkv)
__device__ float g_wot[(size_t)Dn * Dn];                  // rna(w_o)

// ---------------------------------------------------------------------------
// PTX helpers (sm_100 baseline)
// ---------------------------------------------------------------------------
__device__ __forceinline__ uint32_t smem_u32(const void* p) {
    uint32_t a;
    asm("{ .reg .u64 t; cvta.to.shared.u64 t, %1; cvt.u32.u64 %0, t; }"
        : "=r"(a) : "l"(p));
    return a;
}

__device__ __forceinline__ void cp16(uint32_t dst, const void* src) {
    asm volatile("cp.async.cg.shared.global [%0], [%1], 16;"
                 :: "r"(dst), "l"(src));
}
#define CP_COMMIT() asm volatile("cp.async.commit_group;" ::: "memory")
#define CP_WAIT(n)  asm volatile("cp.async.wait_group %0;" :: "n"(n) : "memory")

__device__ __forceinline__ float tf32r(float x) {
    uint32_t u;
    asm("cvt.rna.tf32.f32 %0, %1;" : "=r"(u) : "f"(x));
    return __uint_as_float(u);
}

// ldmatrix on fp32 data viewed as b16 pairs: lane L receives row L/4,
// float-column L%4 of each 8x8-float matrix -> exact tf32 fragment layout.
__device__ __forceinline__ void ldsm4(uint32_t* r, uint32_t addr) {
    asm volatile("ldmatrix.sync.aligned.m8n8.x4.shared.b16 {%0,%1,%2,%3}, [%4];"
                 : "=r"(r[0]), "=r"(r[1]), "=r"(r[2]), "=r"(r[3]) : "r"(addr));
}

__device__ __forceinline__ void mma_tf32(float* d, const uint32_t* a, const uint32_t* b) {
    asm volatile("mma.sync.aligned.m16n8k8.row.col.f32.tf32.tf32.f32 "
                 "{%0,%1,%2,%3}, {%4,%5,%6,%7}, {%8,%9}, {%0,%1,%2,%3};"
                 : "+f"(d[0]), "+f"(d[1]), "+f"(d[2]), "+f"(d[3])
                 : "r"(a[0]), "r"(a[1]), "r"(a[2]), "r"(a[3]), "r"(b[0]), "r"(b[1]));
}

// ---------------------------------------------------------------------------
// Elementwise rna(tf32) pre-pass
// ---------------------------------------------------------------------------
__global__ void __launch_bounds__(256) cvt_kernel(
    const float4* __restrict__ in, float4* __restrict__ outp, int n4)
{
    int i = blockIdx.x * 256 + threadIdx.x;
    if (i >= n4) return;
    float4 v = in[i];
    v.x = tf32r(v.x); v.y = tf32r(v.y); v.z = tf32r(v.z); v.w = tf32r(v.w);
    outp[i] = v;
}

// ---------------------------------------------------------------------------
// tf32 GEMM: C[M,N] = A[M,K] * B[N,K]^T, fp32 accumulate.
// 128x128 CTA tile, BK=32, 8 warps (2x4), warp tile 64x32, 3-stage cp.async,
// SINGLE barrier per K-chunk (refill-before-compute ordering).
// ---------------------------------------------------------------------------
#define GLDS  36
#define GMATF (128 * GLDS)
#define GSTG  (2 * GMATF * 4)
#define G_SMEM (3 * GSTG)

template <int REMAP>
__global__ void __launch_bounds__(256, 2) gemm_tf32(
    const float* __restrict__ A, const float* __restrict__ Bm,
    float* __restrict__ C, int M, int N, int K)
{
    extern __shared__ float sg[];
    const uint32_t sb = smem_u32(sg);
    const int tid = threadIdx.x, lane = tid & 31, wid = tid >> 5;
    const int wm = wid >> 2, wn = wid & 3;
    const int lr = lane >> 2, lc = lane & 3;
    const int bm = blockIdx.y * 128, bn = blockIdx.x * 128;
    const int NC = K >> 5;

    const char* gA = (const char*)(A + (size_t)bm * K);
    const char* gB = (const char*)(Bm + (size_t)bn * K);

    auto fill = [&](int s, int c) {
        const uint32_t base = sb + s * GSTG;
        const int kof = c * 32;
#pragma unroll
        for (int u = 0; u < 4; u++) {
            const int ch = tid + u * 256;
            const int row = ch >> 3, col = (ch & 7) << 2;
            cp16(base + (uint32_t)(row * GLDS + col) * 4,
                 gA + ((size_t)row * K + kof + col) * 4);
            cp16(base + (uint32_t)GMATF * 4 + (uint32_t)(row * GLDS + col) * 4,
                 gB + ((size_t)row * K + kof + col) * 4);
        }
        CP_COMMIT();
    };

    fill(0, 0);
    if (NC > 1) fill(1, 1);

    float acc[4][4][4];
#pragma unroll
    for (int i = 0; i < 4; i++)
#pragma unroll
        for (int j = 0; j < 4; j++)
#pragma unroll
            for (int e = 0; e < 4; e++) acc[i][j][e] = 0.f;

    // ldmatrix lane addressing (float-element offsets)
    const uint32_t aOff = (uint32_t)((wm * 64 + (lane & 15)) * GLDS + ((lane >> 4) << 2)) * 4;
    const uint32_t bOff = (uint32_t)((wn * 32 + (((lane >> 4) & 1) << 3) + (lane & 7)) * GLDS
                                     + (((lane >> 3) & 1) << 2)) * 4;

    for (int c = 0; c < NC; c++) {
        const int s = c % 3;
        if (c < NC - 1) { CP_WAIT(1); } else { CP_WAIT(0); }
        __syncthreads();
        // Barrier above certifies all warps finished reading stage (c+2)%3
        // (read at iter c-1) -> safe to refill it now, overlapping compute.
        if (c + 2 < NC) fill((c + 2) % 3, c + 2);

        const uint32_t aB = sb + s * GSTG + aOff;
        const uint32_t bB = sb + s * GSTG + (uint32_t)GMATF * 4 + bOff;

#pragma unroll
        for (int k0 = 0; k0 < 32; k0 += 8) {
            uint32_t a[4][4], bq[2][4];
#pragma unroll
            for (int i = 0; i < 4; i++)
                ldsm4(a[i], aB + (uint32_t)(i * 16 * GLDS + k0) * 4);
#pragma unroll
            for (int jp = 0; jp < 2; jp++)
                ldsm4(bq[jp], bB + (uint32_t)(jp * 16 * GLDS + k0) * 4);
#pragma unroll
            for (int jp = 0; jp < 2; jp++)
#pragma unroll
                for (int i = 0; i < 4; i++) {
                    mma_tf32(acc[i][2 * jp],     a[i], &bq[jp][0]);
                    mma_tf32(acc[i][2 * jp + 1], a[i], &bq[jp][2]);
                }
        }
        // no trailing barrier: next iteration's top barrier provides it
    }

    const int fc = lc << 1;
#pragma unroll
    for (int i = 0; i < 4; i++) {
#pragma unroll
        for (int j = 0; j < 4; j++) {
            const int n = bn + wn * 32 + j * 8 + fc;
#pragma unroll
            for (int half = 0; half < 2; half++) {
                const int m = bm + wm * 64 + i * 16 + lr + half * 8;
                float2 v = make_float2(acc[i][j][half * 2], acc[i][j][half * 2 + 1]);
                if (REMAP == 0) {
                    v.x = tf32r(v.x); v.y = tf32r(v.y);
                    const int q = n >> 10, h = (n >> 6) & 15, kd = n & 63;
                    const int b = m >> 11, s2 = m & 2047;
                    *(float2*)&g_qkv[((((size_t)q * Bn + b) * Hn + h) * Sn + s2) * DKn + kd] = v;
                } else {
                    *(float2*)&C[(size_t)m * N + n] = v;
                }
            }
        }
    }
}

// ---------------------------------------------------------------------------
// Causal flash attention on tf32 mma.sync.
// CTA = (b, h, 128-row q tile); 8 warps each own 16 S rows (warp-local softmax).
// Double-buffered cp.async K+V, SINGLE barrier per k-tile (refill after the
// top barrier, overlapped with the whole tile's compute).
// ---------------------------------------------------------------------------
#define FQL 68                          // Q/K stride (bank = 4*lr+lc)
#define FVL 72                          // V stride  (bank = 8*lc+lr)
#define FKBYTES (64 * FQL * 4)          // 17408
#define FVBYTES (64 * FVL * 4)          // 18432
#define FSTG (FKBYTES + FVBYTES)        // 35840
#define F_SMEM (128 * FQL * 4 + 2 * FSTG)  // 106496

__global__ void __launch_bounds__(256, 2) flash_tf32()
{
    extern __shared__ float smf[];
    float* Qs = smf;                          // [128][FQL], pre-scaled by 1/8
    const uint32_t sbQ  = smem_u32(smf);
    const uint32_t sbKV = sbQ + 128 * FQL * 4;

    const int qt = (Sn / 128 - 1) - blockIdx.x;   // largest workload first
    const int h = blockIdx.y, b = blockIdx.z;
    const int tid = threadIdx.x;
    const int lane = tid & 31, wid = tid >> 5;
    const int lr = lane >> 2, lc = lane & 3;

    const size_t headoff = (((size_t)b * Hn + h) * Sn) * DKn;
    const size_t plane = (size_t)Bn * Hn * Sn * DKn;
    const float* Qg = g_qkv + headoff;
    const float* Kg = g_qkv + plane + headoff;
    const float* Vg = g_qkv + 2 * plane + headoff;

    auto fillKV = [&](int s, int kt) {
        const uint32_t base = sbKV + s * FSTG;
#pragma unroll
        for (int u = 0; u < 4; u++) {
            const int ch = tid + u * 256;
            const int r = ch >> 4, c = (ch & 15) << 2;
            const float* src = Kg + (size_t)(kt * 64 + r) * DKn + c;
            cp16(base + (uint32_t)(r * FQL + c) * 4, src);
            cp16(base + FKBYTES + (uint32_t)(r * FVL + c) * 4, src + plane);
        }
        CP_COMMIT();
    };

    const int KT = 2 * qt + 2;
    fillKV(0, 0);

#pragma unroll
    for (int u = 0; u < 8; u++) {
        const int idx = tid + u * 256;
        const int r = idx >> 4, c = (idx & 15) << 2;
        float4 q = *(const float4*)(Qg + (size_t)(qt * 128 + r) * DKn + c);
        q.x *= 0.125f; q.y *= 0.125f; q.z *= 0.125f; q.w *= 0.125f;
        *(float4*)(Qs + r * FQL + c) = q;
    }

    float oacc[8][4];
#pragma unroll
    for (int j = 0; j < 8; j++)
#pragma unroll
        for (int e = 0; e < 4; e++) oacc[j][e] = 0.f;
    float m0 = -1e30f, m1 = -1e30f, l0 = 0.f, l1 = 0.f;

    // ldmatrix lane addressing
    const uint32_t qOff = sbQ +
        (uint32_t)((wid * 16 + (lane & 15)) * FQL + ((lane >> 4) << 2)) * 4;
    const uint32_t kOff =
        (uint32_t)(((((lane >> 4) & 1) << 3) + (lane & 7)) * FQL + (((lane >> 3) & 1) << 2)) * 4;

    for (int kt = 0; kt < KT; kt++) {
        const int s = kt & 1;
        CP_WAIT(0);
        __syncthreads();
        // Barrier certifies all warps finished reading stage s^1 at kt-1
        // (and makes the Q-tile stores visible on kt==0) -> refill s^1 now.
        if (kt + 1 < KT) fillKV(s ^ 1, kt + 1);

        const uint32_t ksb = sbKV + s * FSTG;
        const float* Vs = smf + (ksb - sbQ + FKBYTES) / 4;

        // S = Q K^T
        float sacc[8][4];
#pragma unroll
        for (int j = 0; j < 8; j++)
#pragma unroll
            for (int e = 0; e < 4; e++) sacc[j][e] = 0.f;

#pragma unroll
        for (int k0 = 0; k0 < 64; k0 += 8) {
            uint32_t a[4];
            ldsm4(a, qOff + (uint32_t)k0 * 4);
#pragma unroll
            for (int jp = 0; jp < 4; jp++) {
                uint32_t kq[4];
                ldsm4(kq, ksb + kOff + (uint32_t)(jp * 16 * FQL + k0) * 4);
                mma_tf32(sacc[2 * jp],     a, &kq[0]);
                mma_tf32(sacc[2 * jp + 1], a, &kq[2]);
            }
        }

        // Causal mask (only tiles touching the diagonal)
        if (kt * 64 + 63 > qt * 128) {
            const int qr0 = qt * 128 + wid * 16 + lr;
#pragma unroll
            for (int j = 0; j < 8; j++) {
                const int kc = kt * 64 + j * 8 + 2 * lc;
                if (kc     > qr0)     sacc[j][0] = -1e30f;
                if (kc + 1 > qr0)     sacc[j][1] = -1e30f;
                if (kc     > qr0 + 8) sacc[j][2] = -1e30f;
                if (kc + 1 > qr0 + 8) sacc[j][3] = -1e30f;
            }
        }

        // Warp-local online softmax
        float pm0 = -1e30f, pm1 = -1e30f;
#pragma unroll
        for (int j = 0; j < 8; j++) {
            pm0 = fmaxf(pm0, fmaxf(sacc[j][0], sacc[j][1]));
            pm1 = fmaxf(pm1, fmaxf(sacc[j][2], sacc[j][3]));
        }
        pm0 = fmaxf(pm0, __shfl_xor_sync(0xffffffffu, pm0, 1));
        pm0 = fmaxf(pm0, __shfl_xor_sync(0xffffffffu, pm0, 2));
        pm1 = fmaxf(pm1, __shfl_xor_sync(0xffffffffu, pm1, 1));
        pm1 = fmaxf(pm1, __shfl_xor_sync(0xffffffffu, pm1, 2));
        const float nm0 = fmaxf(m0, pm0), nm1 = fmaxf(m1, pm1);

        float sum0 = 0.f, sum1 = 0.f;
#pragma unroll
        for (int j = 0; j < 8; j++) {
            sacc[j][0] = __expf(sacc[j][0] - nm0);
            sacc[j][1] = __expf(sacc[j][1] - nm0);
            sacc[j][2] = __expf(sacc[j][2] - nm1);
            sacc[j][3] = __expf(sacc[j][3] - nm1);
            sum0 += sacc[j][0] + sacc[j][1];
            sum1 += sacc[j][2] + sacc[j][3];
        }
        sum0 += __shfl_xor_sync(0xffffffffu, sum0, 1);
        sum0 += __shfl_xor_sync(0xffffffffu, sum0, 2);
        sum1 += __shfl_xor_sync(0xffffffffu, sum1, 1);
        sum1 += __shfl_xor_sync(0xffffffffu, sum1, 2);

        const float al0 = __expf(m0 - nm0), al1 = __expf(m1 - nm1);
        l0 = l0 * al0 + sum0; l1 = l1 * al1 + sum1;
        m0 = nm0; m1 = nm1;
#pragma unroll
        for (int j = 0; j < 8; j++) {
            oacc[j][0] *= al0; oacc[j][1] *= al0;
            oacc[j][2] *= al1; oacc[j][3] *= al1;
        }

        // O += P V  (P acc-layout -> A-fragment via quad shuffles;
        //            B fragment read directly from natural Vs[s][d])
        const int srcA = (lane & ~3) | (lc >> 1);
        const int srcB = srcA + 2;
#pragma unroll
        for (int jk = 0; jk < 8; jk++) {
            const uint32_t p0 = __float_as_uint(tf32r(sacc[jk][0]));
            const uint32_t p1 = __float_as_uint(tf32r(sacc[jk][1]));
            const uint32_t p2 = __float_as_uint(tf32r(sacc[jk][2]));
            const uint32_t p3 = __float_as_uint(tf32r(sacc[jk][3]));
            uint32_t a[4], x0, x1;
            x0 = __shfl_sync(0xffffffffu, p0, srcA);
            x1 = __shfl_sync(0xffffffffu, p1, srcA);
            a[0] = (lc & 1) ? x1 : x0;
            x0 = __shfl_sync(0xffffffffu, p2, srcA);
            x1 = __shfl_sync(0xffffffffu, p3, srcA);
            a[1] = (lc & 1) ? x1 : x0;
            x0 = __shfl_sync(0xffffffffu, p0, srcB);
            x1 = __shfl_sync(0xffffffffu, p1, srcB);
            a[2] = (lc & 1) ? x1 : x0;
            x0 = __shfl_sync(0xffffffffu, p2, srcB);
            x1 = __shfl_sync(0xffffffffu, p3, srcB);
            a[3] = (lc & 1) ? x1 : x0;

            const int kk = jk * 8;
#pragma unroll
            for (int j2 = 0; j2 < 8; j2++) {
                const int n = j2 * 8 + lr;
                uint32_t bf[2] = { __float_as_uint(Vs[(kk + lc) * FVL + n]),
                                   __float_as_uint(Vs[(kk + lc + 4) * FVL + n]) };
                mma_tf32(oacc[j2], a, bf);
            }
        }
        // no trailing barrier: next iteration's top barrier provides it
    }

    // Epilogue: normalize, rna (feeds out-proj as tf32), write [b][s][h*64+d]
    const float inv0 = 1.f / l0, inv1 = 1.f / l1;
    const int r0 = qt * 128 + wid * 16 + lr;
#pragma unroll
    for (int j2 = 0; j2 < 8; j2++) {
        const int col = h * 64 + j2 * 8 + 2 * lc;
        *(float2*)&g_attn[((size_t)b * Sn + r0) * Dn + col] =
            make_float2(tf32r(oacc[j2][0] * inv0), tf32r(oacc[j2][1] * inv0));
        *(float2*)&g_attn[((size_t)b * Sn + r0 + 8) * Dn + col] =
            make_float2(tf32r(oacc[j2][2] * inv1), tf32r(oacc[j2][3] * inv1));
    }
}

// ---------------------------------------------------------------------------

extern "C" void kernel_launch(void* const* d_in, const int* in_sizes, int n_in,
                              void* d_out, int out_size)
{
    const float* x     = (const float*)d_in[0];  // [B,S,D]
    const float* w_qkv = (const float*)d_in[1];  // [3,H,DK,D]
    const float* w_o   = (const float*)d_in[2];  // [D,D]
    float* out = (float*)d_out;                  // [B,S,D]

    const int M = Bn * Sn;   // 8192

    (void)cudaFuncSetAttribute(flash_tf32,
                               cudaFuncAttributeMaxDynamicSharedMemorySize, F_SMEM);
    (void)cudaFuncSetAttribute(gemm_tf32<0>,
                               cudaFuncAttributeMaxDynamicSharedMemorySize, G_SMEM);
    (void)cudaFuncSetAttribute(gemm_tf32<1>,
                               cudaFuncAttributeMaxDynamicSharedMemorySize, G_SMEM);

    float *xt, *wt, *wot, *attn;
    (void)cudaGetSymbolAddress((void**)&xt, g_xt);
    (void)cudaGetSymbolAddress((void**)&wt, g_wt);
    (void)cudaGetSymbolAddress((void**)&wot, g_wot);
    (void)cudaGetSymbolAddress((void**)&attn, g_attn);

    // 0) rna(tf32) pre-pass on inputs
    {
        int n4 = M * Dn / 4;
        cvt_kernel<<<(n4 + 255) / 256, 256>>>((const float4*)x, (float4*)xt, n4);
        n4 = 3 * Hn * DKn * Dn / 4;
        cvt_kernel<<<(n4 + 255) / 256, 256>>>((const float4*)w_qkv, (float4*)wt, n4);
        n4 = Dn * Dn / 4;
        cvt_kernel<<<(n4 + 255) / 256, 256>>>((const float4*)w_o, (float4*)wot, n4);
    }

    // 1) QKV projection (tf32 mma) -> g_qkv
    {
        dim3 grid(3 * Hn * DKn / 128, M / 128);  // (24, 64)
        gemm_tf32<0><<<grid, 256, G_SMEM>>>(xt, wt, nullptr, M, 3 * Hn * DKn, Dn);
    }

    // 2) Causal flash attention (tf32 mma) -> g_attn
    {
        dim3 grid(Sn / 128, Hn, Bn);  // (16, 16, 4)
        flash_tf32<<<grid, 256, F_SMEM>>>();
    }

    // 3) Output projection (tf32 mma) -> out
    {
        dim3 grid(Dn / 128, M / 128);  // (8, 64)
        gemm_tf32<1><<<grid, 256, G_SMEM>>>(attn, wot, out, M, Dn, Dn);
    }
}